// round 5
// baseline (speedup 1.0000x reference)
#include <cuda_runtime.h>
#include <cuda_bf16.h>

#define NNODES 10000
#define F_IN   256
#define HID    512
#define C_OUT  128
#define NEDGES 320000

// Scratch (allocation-free rule: __device__ globals)
__device__ float g_agg1[NNODES * F_IN];   // 10.24 MB
__device__ float g_h   [NNODES * HID];    // 20.48 MB
__device__ float g_agg2[NNODES * HID];    // 20.48 MB
__device__ int   g_src [NEDGES];
__device__ int   g_dst [NEDGES];
__device__ int   g_is32;                  // 1 if edge_index stored as int32

// ---------------------------------------------------------------------------
// Detect edge dtype: reading as int32 is safe for both layouts (covers <= buf).
// int64-LE values < 2^31 -> all odd int32 words are 0. int32 random indices ->
// odd words are (almost surely) nonzero somewhere in the first 2048.
__global__ void detect_dtype(const int* __restrict__ ei32, int n_check) {
    __shared__ int s_any;
    if (threadIdx.x == 0) s_any = 0;
    __syncthreads();
    int any = 0;
    for (int i = 2 * threadIdx.x + 1; i < n_check; i += 2 * blockDim.x)
        any |= ei32[i];
    if (any) atomicOr(&s_any, 1);
    __syncthreads();
    if (threadIdx.x == 0) g_is32 = (s_any != 0) ? 1 : 0;
}

// Materialize int32 src/dst, clamped to valid range (mis-decode -> rel_err,
// not a crash).
__global__ void convert_edges(const void* __restrict__ ei,
                              int* __restrict__ src, int* __restrict__ dst,
                              int E, int n_nodes) {
    const int is32 = g_is32;
    int e = blockIdx.x * blockDim.x + threadIdx.x;
    int stride = gridDim.x * blockDim.x;
    for (; e < E; e += stride) {
        long long s, d;
        if (is32) {
            const int* p = (const int*)ei;
            s = p[e]; d = p[E + e];
        } else {
            const long long* p = (const long long*)ei;
            s = p[e]; d = p[E + e];
        }
        if (s < 0) s = 0; if (s >= n_nodes) s = n_nodes - 1;
        if (d < 0) d = 0; if (d >= n_nodes) d = n_nodes - 1;
        src[e] = (int)s;
        dst[e] = (int)d;
    }
}

// ---------------------------------------------------------------------------
__global__ void zero_kernel(float4* __restrict__ p, int n4) {
    int i = blockIdx.x * blockDim.x + threadIdx.x;
    int stride = gridDim.x * blockDim.x;
    for (; i < n4; i += stride) p[i] = make_float4(0.f, 0.f, 0.f, 0.f);
}

// ---------------------------------------------------------------------------
// Warp-per-edge scatter: agg[dst] += x[src]. float4 vector atomics (sm_90+).
__global__ void scatter_add(const float* __restrict__ x,
                            const int* __restrict__ src,
                            const int* __restrict__ dst,
                            float* __restrict__ agg, int E, int F) {
    int gtid   = blockIdx.x * blockDim.x + threadIdx.x;
    int warp   = gtid >> 5;
    int lane   = threadIdx.x & 31;
    int nwarps = (gridDim.x * blockDim.x) >> 5;
    int f4     = F >> 2;
    for (int e = warp; e < E; e += nwarps) {
        int s = src[e];
        int d = dst[e];
        const float4* xs = (const float4*)(x + (size_t)s * F);
        float4*       ad = (float4*)(agg + (size_t)d * F);
        for (int i = lane; i < f4; i += 32) {
            float4 v = xs[i];
            atomicAdd(ad + i, v);   // vector RED on sm_90+
        }
    }
}

// ---------------------------------------------------------------------------
// Fused dual GEMM: C = act(A1@B1 + A2@B2 + bias)
// A: [M,K] row-major (two of them, same K); B: [K,Nn] row-major.
// BM=128, BN=64, BK=16, 256 threads, per-thread 8x4 micro-tile.
template <bool RELU>
__global__ void __launch_bounds__(256, 2)
gemm_dual(const float* __restrict__ A1, const float* __restrict__ B1,
          const float* __restrict__ A2, const float* __restrict__ B2,
          const float* __restrict__ bias, float* __restrict__ C,
          int M, int K, int Nn) {
    constexpr int BM = 128, BN = 64, BK = 16;
    __shared__ float As[BK][BM + 4];   // +4 pad reduces store bank conflicts
    __shared__ float Bs[BK][BN];

    const int tid = threadIdx.x;
    const int tx  = tid & 15;          // 16 col groups (x4 cols)
    const int ty  = tid >> 4;          // 16 row groups (x8 rows)
    const int bm  = blockIdx.y * BM;
    const int bn  = blockIdx.x * BN;

    float acc[8][4];
#pragma unroll
    for (int i = 0; i < 8; ++i)
#pragma unroll
        for (int j = 0; j < 4; ++j) acc[i][j] = 0.f;

#pragma unroll
    for (int phase = 0; phase < 2; ++phase) {
        const float* A = phase ? A2 : A1;
        const float* B = phase ? B2 : B1;

        for (int kk = 0; kk < K; kk += BK) {
            // Load A tile 128x16 (512 float4, 2 per thread), store transposed.
#pragma unroll
            for (int r = 0; r < 2; ++r) {
                int idx = tid + r * 256;     // 0..511
                int row = idx >> 2;          // 0..127
                int kq  = idx & 3;           // 0..3 (float4 within row)
                float4 v = make_float4(0.f, 0.f, 0.f, 0.f);
                int grow = bm + row;
                if (grow < M)
                    v = *(const float4*)(A + (size_t)grow * K + kk + kq * 4);
                As[kq * 4 + 0][row] = v.x;
                As[kq * 4 + 1][row] = v.y;
                As[kq * 4 + 2][row] = v.z;
                As[kq * 4 + 3][row] = v.w;
            }
            // Load B tile 16x64 (256 float4, 1 per thread).
            {
                int row = tid >> 4;          // 0..15 (k)
                int cq  = tid & 15;          // 0..15 (float4 col group)
                float4 v = *(const float4*)(B + (size_t)(kk + row) * Nn + bn + cq * 4);
                *(float4*)&Bs[row][cq * 4] = v;
            }
            __syncthreads();

#pragma unroll
            for (int k = 0; k < BK; ++k) {
                float4 a0 = *(const float4*)&As[k][ty * 8];
                float4 a1 = *(const float4*)&As[k][ty * 8 + 4];
                float4 bv = *(const float4*)&Bs[k][tx * 4];
                float a[8] = {a0.x, a0.y, a0.z, a0.w, a1.x, a1.y, a1.z, a1.w};
                float b[4] = {bv.x, bv.y, bv.z, bv.w};
#pragma unroll
                for (int i = 0; i < 8; ++i)
#pragma unroll
                    for (int j = 0; j < 4; ++j)
                        acc[i][j] = fmaf(a[i], b[j], acc[i][j]);
            }
            __syncthreads();
        }
    }

    // Epilogue: bias (+relu), vectorized store.
    float4 bb = *(const float4*)(bias + bn + tx * 4);
#pragma unroll
    for (int i = 0; i < 8; ++i) {
        int row = bm + ty * 8 + i;
        if (row < M) {
            float4 o;
            o.x = acc[i][0] + bb.x;
            o.y = acc[i][1] + bb.y;
            o.z = acc[i][2] + bb.z;
            o.w = acc[i][3] + bb.w;
            if (RELU) {
                o.x = fmaxf(o.x, 0.f);
                o.y = fmaxf(o.y, 0.f);
                o.z = fmaxf(o.z, 0.f);
                o.w = fmaxf(o.w, 0.f);
            }
            *(float4*)(C + (size_t)row * Nn + bn + tx * 4) = o;
        }
    }
}

// ---------------------------------------------------------------------------
extern "C" void kernel_launch(void* const* d_in, const int* in_sizes, int n_in,
                              void* d_out, int out_size) {
    const float* x   = (const float*)d_in[0];
    const void*  ei  = d_in[1];
    const float* W1l = (const float*)d_in[2];
    const float* b1  = (const float*)d_in[3];
    const float* W1r = (const float*)d_in[4];
    const float* W2l = (const float*)d_in[5];
    const float* b2  = (const float*)d_in[6];
    const float* W2r = (const float*)d_in[7];
    float*       out = (float*)d_out;

    const int M = in_sizes[0] / F_IN;    // 10000
    const int E = in_sizes[1] / 2;       // 320000

    float *agg1, *h, *agg2;
    int *srcp, *dstp;
    cudaGetSymbolAddress((void**)&agg1, g_agg1);
    cudaGetSymbolAddress((void**)&h,    g_h);
    cudaGetSymbolAddress((void**)&agg2, g_agg2);
    cudaGetSymbolAddress((void**)&srcp, g_src);
    cudaGetSymbolAddress((void**)&dstp, g_dst);

    // ---- Edge decode (dtype-adaptive) ----
    detect_dtype<<<1, 256>>>((const int*)ei, (2 * E < 2048) ? 2 * E : 2048);
    convert_edges<<<(E + 255) / 256, 256>>>(ei, srcp, dstp, E, M);

    // ---- Layer 1 ----
    {
        int n4 = M * F_IN / 4;
        zero_kernel<<<(n4 + 255) / 256, 256>>>((float4*)agg1, n4);
    }
    scatter_add<<<2048, 256>>>(x, srcp, dstp, agg1, E, F_IN);
    {
        dim3 grid(HID / 64, (M + 127) / 128);
        gemm_dual<true><<<grid, 256>>>(agg1, W1l, x, W1r, b1, h, M, F_IN, HID);
    }

    // ---- Layer 2 ----
    {
        int n4 = M * HID / 4;
        zero_kernel<<<(n4 + 255) / 256, 256>>>((float4*)agg2, n4);
    }
    scatter_add<<<2048, 256>>>(h, srcp, dstp, agg2, E, HID);
    {
        dim3 grid(C_OUT / 64, (M + 127) / 128);
        gemm_dual<false><<<grid, 256>>>(agg2, W2l, h, W2r, b2, out, M, HID, C_OUT);
    }
}

// round 6
// speedup vs baseline: 1.4282x; 1.4282x over previous
#include <cuda_runtime.h>
#include <cuda_bf16.h>

#define NNODES 10000
#define F_IN   256
#define HID    512
#define C_OUT  128
#define NEDGES 320000

// Scratch (allocation-free rule: __device__ globals)
__device__ float g_agg1[NNODES * F_IN];    // agg(x)      10.24 MB
__device__ float g_h   [NNODES * HID];     // layer1 out  20.48 MB
__device__ float g_P   [NNODES * C_OUT];   // h @ W2l      5.12 MB
__device__ int   g_src [NEDGES];
__device__ int   g_dst [NEDGES];
__device__ int   g_deg [NNODES];
__device__ int   g_rowptr[NNODES + 1];
__device__ int   g_cursor[NNODES];
__device__ int   g_csr [NEDGES];
__device__ int   g_is32;                   // 1 if edge_index stored as int32

// ---------------------------------------------------------------------------
// Detect edge dtype: reading as int32 is safe for both layouts.
// int64-LE values < 2^31 -> all odd int32 words are 0.
__global__ void detect_dtype(const int* __restrict__ ei32, int n_check) {
    __shared__ int s_any;
    if (threadIdx.x == 0) s_any = 0;
    __syncthreads();
    int any = 0;
    for (int i = 2 * threadIdx.x + 1; i < n_check; i += 2 * blockDim.x)
        any |= ei32[i];
    if (any) atomicOr(&s_any, 1);
    __syncthreads();
    if (threadIdx.x == 0) g_is32 = (s_any != 0) ? 1 : 0;
}

__global__ void zero_deg() {
    int i = blockIdx.x * blockDim.x + threadIdx.x;
    if (i < NNODES) g_deg[i] = 0;
}

// Materialize int32 src/dst (clamped) + degree histogram in one pass.
__global__ void convert_edges_hist(const void* __restrict__ ei, int E) {
    const int is32 = g_is32;
    int e = blockIdx.x * blockDim.x + threadIdx.x;
    int stride = gridDim.x * blockDim.x;
    for (; e < E; e += stride) {
        long long s, d;
        if (is32) {
            const int* p = (const int*)ei;
            s = p[e]; d = p[E + e];
        } else {
            const long long* p = (const long long*)ei;
            s = p[e]; d = p[E + e];
        }
        if (s < 0) s = 0; if (s >= NNODES) s = NNODES - 1;
        if (d < 0) d = 0; if (d >= NNODES) d = NNODES - 1;
        g_src[e] = (int)s;
        g_dst[e] = (int)d;
        atomicAdd(&g_deg[(int)d], 1);
    }
}

// Single-block exclusive scan of g_deg -> g_rowptr (+ cursor copy).
// 1024 threads x 16 elems = 16384 >= NNODES.
__global__ void build_rowptr() {
    __shared__ int sums[1024];
    const int t = threadIdx.x;
    const int base = t * 16;
    int local[16];
    int s = 0;
#pragma unroll
    for (int i = 0; i < 16; ++i) {
        int idx = base + i;
        int v = (idx < NNODES) ? g_deg[idx] : 0;
        local[i] = s;
        s += v;
    }
    sums[t] = s;
    __syncthreads();
    for (int off = 1; off < 1024; off <<= 1) {
        int v = (t >= off) ? sums[t - off] : 0;
        __syncthreads();
        sums[t] += v;
        __syncthreads();
    }
    int excl = (t == 0) ? 0 : sums[t - 1];
#pragma unroll
    for (int i = 0; i < 16; ++i) {
        int idx = base + i;
        if (idx < NNODES) {
            int rp = excl + local[i];
            g_rowptr[idx] = rp;
            g_cursor[idx] = rp;
        }
    }
    if (t == 1023) g_rowptr[NNODES] = sums[1023];
}

__global__ void fill_csr(int E) {
    int e = blockIdx.x * blockDim.x + threadIdx.x;
    int stride = gridDim.x * blockDim.x;
    for (; e < E; e += stride) {
        int d = g_dst[e];
        int pos = atomicAdd(&g_cursor[d], 1);
        g_csr[pos] = g_src[e];
    }
}

// ---------------------------------------------------------------------------
// CSR gather-sum, warp per destination node. NF4 float4 per lane
// (row width F = NF4*128 floats). If ACC, accumulates onto existing OUT row.
template <int NF4, bool ACC>
__global__ void gather_rows(const float* __restrict__ X,
                            float* __restrict__ OUT, int Nn) {
    constexpr int F = NF4 * 128;
    int node = (blockIdx.x * blockDim.x + threadIdx.x) >> 5;
    if (node >= Nn) return;
    int lane = threadIdx.x & 31;
    int r0 = g_rowptr[node];
    int r1 = g_rowptr[node + 1];

    float4 acc[NF4];
    if (ACC) {
        const float4* o = (const float4*)(OUT + (size_t)node * F);
#pragma unroll
        for (int j = 0; j < NF4; ++j) acc[j] = o[lane + 32 * j];
    } else {
#pragma unroll
        for (int j = 0; j < NF4; ++j) acc[j] = make_float4(0.f, 0.f, 0.f, 0.f);
    }

    int e = r0;
    for (; e + 1 < r1; e += 2) {
        int s0 = g_csr[e];
        int s1 = g_csr[e + 1];
        const float4* p0 = (const float4*)(X + (size_t)s0 * F);
        const float4* p1 = (const float4*)(X + (size_t)s1 * F);
#pragma unroll
        for (int j = 0; j < NF4; ++j) {
            float4 a = p0[lane + 32 * j];
            float4 b = p1[lane + 32 * j];
            acc[j].x += a.x + b.x;
            acc[j].y += a.y + b.y;
            acc[j].z += a.z + b.z;
            acc[j].w += a.w + b.w;
        }
    }
    if (e < r1) {
        const float4* p0 = (const float4*)(X + (size_t)g_csr[e] * F);
#pragma unroll
        for (int j = 0; j < NF4; ++j) {
            float4 a = p0[lane + 32 * j];
            acc[j].x += a.x; acc[j].y += a.y;
            acc[j].z += a.z; acc[j].w += a.w;
        }
    }

    float4* o = (float4*)(OUT + (size_t)node * F);
#pragma unroll
    for (int j = 0; j < NF4; ++j) o[lane + 32 * j] = acc[j];
}

// ---------------------------------------------------------------------------
// Fused dual GEMM: C = act(A1@B1 + A2@B2 + bias)  (layer 1)
template <bool RELU>
__global__ void __launch_bounds__(256, 2)
gemm_dual(const float* __restrict__ A1, const float* __restrict__ B1,
          const float* __restrict__ A2, const float* __restrict__ B2,
          const float* __restrict__ bias, float* __restrict__ C,
          int M, int K, int Nn) {
    constexpr int BM = 128, BN = 64, BK = 16;
    __shared__ float As[BK][BM + 4];
    __shared__ float Bs[BK][BN];

    const int tid = threadIdx.x;
    const int tx  = tid & 15;
    const int ty  = tid >> 4;
    const int bm  = blockIdx.y * BM;
    const int bn  = blockIdx.x * BN;

    float acc[8][4];
#pragma unroll
    for (int i = 0; i < 8; ++i)
#pragma unroll
        for (int j = 0; j < 4; ++j) acc[i][j] = 0.f;

#pragma unroll
    for (int phase = 0; phase < 2; ++phase) {
        const float* A = phase ? A2 : A1;
        const float* B = phase ? B2 : B1;

        for (int kk = 0; kk < K; kk += BK) {
#pragma unroll
            for (int r = 0; r < 2; ++r) {
                int idx = tid + r * 256;
                int row = idx >> 2;
                int kq  = idx & 3;
                float4 v = make_float4(0.f, 0.f, 0.f, 0.f);
                int grow = bm + row;
                if (grow < M)
                    v = *(const float4*)(A + (size_t)grow * K + kk + kq * 4);
                As[kq * 4 + 0][row] = v.x;
                As[kq * 4 + 1][row] = v.y;
                As[kq * 4 + 2][row] = v.z;
                As[kq * 4 + 3][row] = v.w;
            }
            {
                int row = tid >> 4;
                int cq  = tid & 15;
                float4 v = *(const float4*)(B + (size_t)(kk + row) * Nn + bn + cq * 4);
                *(float4*)&Bs[row][cq * 4] = v;
            }
            __syncthreads();

#pragma unroll
            for (int k = 0; k < BK; ++k) {
                float4 a0 = *(const float4*)&As[k][ty * 8];
                float4 a1 = *(const float4*)&As[k][ty * 8 + 4];
                float4 bv = *(const float4*)&Bs[k][tx * 4];
                float a[8] = {a0.x, a0.y, a0.z, a0.w, a1.x, a1.y, a1.z, a1.w};
                float b[4] = {bv.x, bv.y, bv.z, bv.w};
#pragma unroll
                for (int i = 0; i < 8; ++i)
#pragma unroll
                    for (int j = 0; j < 4; ++j)
                        acc[i][j] = fmaf(a[i], b[j], acc[i][j]);
            }
            __syncthreads();
        }
    }

    float4 bb = *(const float4*)(bias + bn + tx * 4);
#pragma unroll
    for (int i = 0; i < 8; ++i) {
        int row = bm + ty * 8 + i;
        if (row < M) {
            float4 o;
            o.x = acc[i][0] + bb.x;
            o.y = acc[i][1] + bb.y;
            o.z = acc[i][2] + bb.z;
            o.w = acc[i][3] + bb.w;
            if (RELU) {
                o.x = fmaxf(o.x, 0.f);
                o.y = fmaxf(o.y, 0.f);
                o.z = fmaxf(o.z, 0.f);
                o.w = fmaxf(o.w, 0.f);
            }
            *(float4*)(C + (size_t)row * Nn + bn + tx * 4) = o;
        }
    }
}

// ---------------------------------------------------------------------------
// Shared-A two-output GEMM (layer 2): C1 = A@B1,  C2 = A@B2 + bias2.
__global__ void __launch_bounds__(256, 2)
gemm_twoB(const float* __restrict__ A,
          const float* __restrict__ B1, const float* __restrict__ B2,
          const float* __restrict__ bias2,
          float* __restrict__ C1, float* __restrict__ C2,
          int M, int K, int Nn) {
    constexpr int BM = 128, BN = 64, BK = 16;
    __shared__ float As [BK][BM + 4];
    __shared__ float Bs1[BK][BN];
    __shared__ float Bs2[BK][BN];

    const int tid = threadIdx.x;
    const int tx  = tid & 15;
    const int ty  = tid >> 4;
    const int bm  = blockIdx.y * BM;
    const int bn  = blockIdx.x * BN;

    float acc1[8][4], acc2[8][4];
#pragma unroll
    for (int i = 0; i < 8; ++i)
#pragma unroll
        for (int j = 0; j < 4; ++j) { acc1[i][j] = 0.f; acc2[i][j] = 0.f; }

    for (int kk = 0; kk < K; kk += BK) {
#pragma unroll
        for (int r = 0; r < 2; ++r) {
            int idx = tid + r * 256;
            int row = idx >> 2;
            int kq  = idx & 3;
            float4 v = make_float4(0.f, 0.f, 0.f, 0.f);
            int grow = bm + row;
            if (grow < M)
                v = *(const float4*)(A + (size_t)grow * K + kk + kq * 4);
            As[kq * 4 + 0][row] = v.x;
            As[kq * 4 + 1][row] = v.y;
            As[kq * 4 + 2][row] = v.z;
            As[kq * 4 + 3][row] = v.w;
        }
        {
            int row = tid >> 4;
            int cq  = tid & 15;
            float4 v1 = *(const float4*)(B1 + (size_t)(kk + row) * Nn + bn + cq * 4);
            float4 v2 = *(const float4*)(B2 + (size_t)(kk + row) * Nn + bn + cq * 4);
            *(float4*)&Bs1[row][cq * 4] = v1;
            *(float4*)&Bs2[row][cq * 4] = v2;
        }
        __syncthreads();

#pragma unroll
        for (int k = 0; k < BK; ++k) {
            float4 a0 = *(const float4*)&As[k][ty * 8];
            float4 a1 = *(const float4*)&As[k][ty * 8 + 4];
            float4 b1 = *(const float4*)&Bs1[k][tx * 4];
            float4 b2 = *(const float4*)&Bs2[k][tx * 4];
            float a[8]  = {a0.x, a0.y, a0.z, a0.w, a1.x, a1.y, a1.z, a1.w};
            float v1[4] = {b1.x, b1.y, b1.z, b1.w};
            float v2[4] = {b2.x, b2.y, b2.z, b2.w};
#pragma unroll
            for (int i = 0; i < 8; ++i) {
#pragma unroll
                for (int j = 0; j < 4; ++j) {
                    acc1[i][j] = fmaf(a[i], v1[j], acc1[i][j]);
                    acc2[i][j] = fmaf(a[i], v2[j], acc2[i][j]);
                }
            }
        }
        __syncthreads();
    }

    float4 bb = *(const float4*)(bias2 + bn + tx * 4);
#pragma unroll
    for (int i = 0; i < 8; ++i) {
        int row = bm + ty * 8 + i;
        if (row < M) {
            float4 o1, o2;
            o1.x = acc1[i][0]; o1.y = acc1[i][1];
            o1.z = acc1[i][2]; o1.w = acc1[i][3];
            o2.x = acc2[i][0] + bb.x;
            o2.y = acc2[i][1] + bb.y;
            o2.z = acc2[i][2] + bb.z;
            o2.w = acc2[i][3] + bb.w;
            *(float4*)(C1 + (size_t)row * Nn + bn + tx * 4) = o1;
            *(float4*)(C2 + (size_t)row * Nn + bn + tx * 4) = o2;
        }
    }
}

// ---------------------------------------------------------------------------
extern "C" void kernel_launch(void* const* d_in, const int* in_sizes, int n_in,
                              void* d_out, int out_size) {
    const float* x   = (const float*)d_in[0];
    const void*  ei  = d_in[1];
    const float* W1l = (const float*)d_in[2];
    const float* b1  = (const float*)d_in[3];
    const float* W1r = (const float*)d_in[4];
    const float* W2l = (const float*)d_in[5];
    const float* b2  = (const float*)d_in[6];
    const float* W2r = (const float*)d_in[7];
    float*       out = (float*)d_out;

    const int M = in_sizes[0] / F_IN;    // 10000
    const int E = in_sizes[1] / 2;       // 320000

    float *agg1, *h, *P;
    cudaGetSymbolAddress((void**)&agg1, g_agg1);
    cudaGetSymbolAddress((void**)&h,    g_h);
    cudaGetSymbolAddress((void**)&P,    g_P);

    // ---- CSR build ----
    detect_dtype<<<1, 256>>>((const int*)ei, (2 * E < 2048) ? 2 * E : 2048);
    zero_deg<<<(NNODES + 255) / 256, 256>>>();
    convert_edges_hist<<<(E + 255) / 256, 256>>>(ei, E);
    build_rowptr<<<1, 1024>>>();
    fill_csr<<<(E + 255) / 256, 256>>>(E);

    // ---- Layer 1: agg1 = segsum(x); h = relu(agg1@W1l + x@W1r + b1) ----
    gather_rows<2, false><<<(M * 32 + 255) / 256, 256>>>(x, agg1, M);
    {
        dim3 grid(HID / 64, (M + 127) / 128);
        gemm_dual<true><<<grid, 256>>>(agg1, W1l, x, W1r, b1, h, M, F_IN, HID);
    }

    // ---- Layer 2 (linearity reorder): P = h@W2l; out = h@W2r + b2;
    //      out += segsum(P)  (agg(h)@W2l == agg(h@W2l)) ----
    {
        dim3 grid(C_OUT / 64, (M + 127) / 128);
        gemm_twoB<<<grid, 256>>>(h, W2l, W2r, b2, P, out, M, HID, C_OUT);
    }
    gather_rows<1, true><<<(M * 32 + 255) / 256, 256>>>(P, out, M);
}

// round 8
// speedup vs baseline: 2.3170x; 1.6223x over previous
#include <cuda_runtime.h>
#include <cuda_bf16.h>
#include <cstdint>

#define NNODES 10000
#define F_IN   256
#define HID    512
#define C_OUT  128
#define NEDGES 320000
#define KCAT   512            // K for both fused GEMMs

// ---------------------------------------------------------------------------
// Scratch (allocation-free rule: __device__ globals)
// ---------------------------------------------------------------------------
__device__ __align__(1024) float g_agg1[NNODES * F_IN];          // agg(x) fp32
__device__ __align__(1024) float g_P   [NNODES * C_OUT];         // h @ W2l fp32
__device__ __align__(1024) __nv_bfloat16 g_A1h[NNODES * KCAT];   // [agg1|x] hi
__device__ __align__(1024) __nv_bfloat16 g_A1l[NNODES * KCAT];   // [agg1|x] lo
__device__ __align__(1024) __nv_bfloat16 g_Hh [NNODES * KCAT];   // h hi
__device__ __align__(1024) __nv_bfloat16 g_Hl [NNODES * KCAT];   // h lo
__device__ __align__(1024) __nv_bfloat16 g_B1h[HID * KCAT];      // [W1l;W1r]^T hi  [N=512][K=512]
__device__ __align__(1024) __nv_bfloat16 g_B1l[HID * KCAT];
__device__ __align__(1024) __nv_bfloat16 g_B2h[(2 * C_OUT) * KCAT]; // [W2l|W2r]^T hi [N=256][K=512]
__device__ __align__(1024) __nv_bfloat16 g_B2l[(2 * C_OUT) * KCAT];
__device__ int g_src[NEDGES];
__device__ int g_dst[NEDGES];
__device__ int g_deg[NNODES];
__device__ int g_rowptr[NNODES + 1];
__device__ int g_cursor[NNODES];
__device__ int g_csr[NEDGES];
__device__ int g_is32;

// ---------------------------------------------------------------------------
// PTX helpers (all plain sm_80+ PTX; no sm_103a-only features)
// ---------------------------------------------------------------------------
__device__ __forceinline__ uint32_t smem_u32(const void* p) {
    uint32_t a;
    asm("{ .reg .u64 t; cvta.to.shared.u64 t, %1; cvt.u32.u64 %0, t; }"
        : "=r"(a) : "l"(p));
    return a;
}
#define CP_ASYNC16(dst, src, sz) \
    asm volatile("cp.async.cg.shared.global [%0], [%1], 16, %2;" \
                 :: "r"(dst), "l"(src), "r"(sz) : "memory")
#define CP_COMMIT() asm volatile("cp.async.commit_group;" ::: "memory")
#define CP_WAIT0()  asm volatile("cp.async.wait_group 0;" ::: "memory")
#define LDSM_X4(r0, r1, r2, r3, addr) \
    asm volatile("ldmatrix.sync.aligned.m8n8.x4.shared.b16 {%0,%1,%2,%3}, [%4];" \
                 : "=r"(r0), "=r"(r1), "=r"(r2), "=r"(r3) : "r"(addr))

__device__ __forceinline__ void mma16816(float c[4],
                                         uint32_t a0, uint32_t a1, uint32_t a2, uint32_t a3,
                                         uint32_t b0, uint32_t b1) {
    asm volatile(
        "mma.sync.aligned.m16n8k16.row.col.f32.bf16.bf16.f32 "
        "{%0,%1,%2,%3}, {%4,%5,%6,%7}, {%8,%9}, {%0,%1,%2,%3};"
        : "+f"(c[0]), "+f"(c[1]), "+f"(c[2]), "+f"(c[3])
        : "r"(a0), "r"(a1), "r"(a2), "r"(a3), "r"(b0), "r"(b1));
}

__device__ __forceinline__ uint32_t swz(uint32_t off) {   // SW128-style XOR
    return off ^ ((off >> 3) & 0x70);
}

__device__ __forceinline__ void split2(float a, float b, uint32_t& h2o, uint32_t& l2o) {
    __nv_bfloat162 hv, lv;
    hv.x = __float2bfloat16(a);
    hv.y = __float2bfloat16(b);
    lv.x = __float2bfloat16(a - __bfloat162float(hv.x));
    lv.y = __float2bfloat16(b - __bfloat162float(hv.y));
    h2o = *reinterpret_cast<uint32_t*>(&hv);
    l2o = *reinterpret_cast<uint32_t*>(&lv);
}

// ---------------------------------------------------------------------------
// Edge decode + CSR build
// ---------------------------------------------------------------------------
__global__ void detect_dtype(const int* __restrict__ ei32, int n_check) {
    __shared__ int s_any;
    if (threadIdx.x == 0) s_any = 0;
    __syncthreads();
    int any = 0;
    for (int i = 2 * threadIdx.x + 1; i < n_check; i += 2 * blockDim.x)
        any |= ei32[i];
    if (any) atomicOr(&s_any, 1);
    __syncthreads();
    if (threadIdx.x == 0) g_is32 = (s_any != 0) ? 1 : 0;
}

__global__ void zero_deg() {
    int i = blockIdx.x * blockDim.x + threadIdx.x;
    if (i < NNODES) g_deg[i] = 0;
}

__global__ void convert_edges_hist(const void* __restrict__ ei, int E) {
    const int is32 = g_is32;
    int e = blockIdx.x * blockDim.x + threadIdx.x;
    int stride = gridDim.x * blockDim.x;
    for (; e < E; e += stride) {
        long long s, d;
        if (is32) {
            const int* p = (const int*)ei;
            s = p[e]; d = p[E + e];
        } else {
            const long long* p = (const long long*)ei;
            s = p[e]; d = p[E + e];
        }
        if (s < 0) s = 0; if (s >= NNODES) s = NNODES - 1;
        if (d < 0) d = 0; if (d >= NNODES) d = NNODES - 1;
        g_src[e] = (int)s;
        g_dst[e] = (int)d;
        atomicAdd(&g_deg[(int)d], 1);
    }
}

// Warp-shuffle block scan: 1024 threads x 16 elems.
__global__ void build_rowptr() {
    __shared__ int wsum[32];
    const int t = threadIdx.x;
    const int lane = t & 31, w = t >> 5;
    const int base = t * 16;
    int local[16];
    int s = 0;
#pragma unroll
    for (int i = 0; i < 16; ++i) {
        int idx = base + i;
        int v = (idx < NNODES) ? g_deg[idx] : 0;
        local[i] = s; s += v;
    }
    int inc = s;
#pragma unroll
    for (int o = 1; o < 32; o <<= 1) {
        int v = __shfl_up_sync(0xffffffffu, inc, o);
        if (lane >= o) inc += v;
    }
    if (lane == 31) wsum[w] = inc;
    __syncthreads();
    if (w == 0) {
        int v2 = wsum[lane];
#pragma unroll
        for (int o = 1; o < 32; o <<= 1) {
            int u = __shfl_up_sync(0xffffffffu, v2, o);
            if (lane >= o) v2 += u;
        }
        wsum[lane] = v2;
    }
    __syncthreads();
    int excl = inc - s + (w ? wsum[w - 1] : 0);
#pragma unroll
    for (int i = 0; i < 16; ++i) {
        int idx = base + i;
        if (idx < NNODES) {
            int rp = excl + local[i];
            g_rowptr[idx] = rp;
            g_cursor[idx] = rp;
        }
    }
    if (t == 1023) g_rowptr[NNODES] = wsum[31];
}

__global__ void fill_csr(int E) {
    int e = blockIdx.x * blockDim.x + threadIdx.x;
    int stride = gridDim.x * blockDim.x;
    for (; e < E; e += stride) {
        int d = g_dst[e];
        int pos = atomicAdd(&g_cursor[d], 1);
        g_csr[pos] = g_src[e];
    }
}

// ---------------------------------------------------------------------------
// CSR gather-sum, warp per destination node.
// ---------------------------------------------------------------------------
template <int NF4, bool ACC>
__global__ void gather_rows(const float* __restrict__ X,
                            float* __restrict__ OUT, int Nn) {
    constexpr int F = NF4 * 128;
    int node = (blockIdx.x * blockDim.x + threadIdx.x) >> 5;
    if (node >= Nn) return;
    int lane = threadIdx.x & 31;
    int r0 = g_rowptr[node];
    int r1 = g_rowptr[node + 1];

    float4 acc[NF4];
    if (ACC) {
        const float4* o = (const float4*)(OUT + (size_t)node * F);
#pragma unroll
        for (int j = 0; j < NF4; ++j) acc[j] = o[lane + 32 * j];
    } else {
#pragma unroll
        for (int j = 0; j < NF4; ++j) acc[j] = make_float4(0.f, 0.f, 0.f, 0.f);
    }

    int e = r0;
    for (; e + 1 < r1; e += 2) {
        int s0 = g_csr[e];
        int s1 = g_csr[e + 1];
        const float4* p0 = (const float4*)(X + (size_t)s0 * F);
        const float4* p1 = (const float4*)(X + (size_t)s1 * F);
#pragma unroll
        for (int j = 0; j < NF4; ++j) {
            float4 a = p0[lane + 32 * j];
            float4 b = p1[lane + 32 * j];
            acc[j].x += a.x + b.x;
            acc[j].y += a.y + b.y;
            acc[j].z += a.z + b.z;
            acc[j].w += a.w + b.w;
        }
    }
    if (e < r1) {
        const float4* p0 = (const float4*)(X + (size_t)g_csr[e] * F);
#pragma unroll
        for (int j = 0; j < NF4; ++j) {
            float4 a = p0[lane + 32 * j];
            acc[j].x += a.x; acc[j].y += a.y;
            acc[j].z += a.z; acc[j].w += a.w;
        }
    }

    float4* o = (float4*)(OUT + (size_t)node * F);
#pragma unroll
    for (int j = 0; j < NF4; ++j) o[lane + 32 * j] = acc[j];
}

// ---------------------------------------------------------------------------
// Pre-conversion kernels (fp32 -> split bf16, weights transposed to [N][K])
// ---------------------------------------------------------------------------
__global__ void build_A1(const float* __restrict__ x, int M) {
    // g_A1h/l[m][k]: k<256 -> agg1[m][k], k>=256 -> x[m][k-256]
    int p = blockIdx.x * blockDim.x + threadIdx.x;
    if (p >= M * 256) return;
    int m = p >> 8;
    int col = (p & 255) * 2;
    float a, b;
    if (col < 256) {
        a = g_agg1[m * 256 + col];
        b = g_agg1[m * 256 + col + 1];
    } else {
        a = x[m * 256 + col - 256];
        b = x[m * 256 + col - 255];
    }
    uint32_t h2, l2;
    split2(a, b, h2, l2);
    *(uint32_t*)(g_A1h + (size_t)m * KCAT + col) = h2;
    *(uint32_t*)(g_A1l + (size_t)m * KCAT + col) = l2;
}

__global__ void build_Bt1(const float* __restrict__ W1l, const float* __restrict__ W1r) {
    // g_B1h/l[n][k], n<512, k<512: k<256 ? W1l[k][n] : W1r[k-256][n]
    int p = blockIdx.x * blockDim.x + threadIdx.x;
    if (p >= 512 * 256) return;
    int n = p >> 8;
    int k = (p & 255) * 2;
    float a, b;
    if (k < 256) { a = W1l[k * 512 + n]; b = W1l[(k + 1) * 512 + n]; }
    else         { a = W1r[(k - 256) * 512 + n]; b = W1r[(k - 255) * 512 + n]; }
    uint32_t h2, l2;
    split2(a, b, h2, l2);
    *(uint32_t*)(g_B1h + (size_t)n * KCAT + k) = h2;
    *(uint32_t*)(g_B1l + (size_t)n * KCAT + k) = l2;
}

__global__ void build_Bt2(const float* __restrict__ W2l, const float* __restrict__ W2r) {
    // g_B2h/l[n][k], n<256, k<512: n<128 ? W2l[k][n] : W2r[k][n-128]
    int p = blockIdx.x * blockDim.x + threadIdx.x;
    if (p >= 256 * 256) return;
    int n = p >> 8;
    int k = (p & 255) * 2;
    const float* W = (n < 128) ? W2l : W2r;
    int nn = n & 127;
    float a = W[k * 128 + nn];
    float b = W[(k + 1) * 128 + nn];
    uint32_t h2, l2;
    split2(a, b, h2, l2);
    *(uint32_t*)(g_B2h + (size_t)n * KCAT + k) = h2;
    *(uint32_t*)(g_B2l + (size_t)n * KCAT + k) = l2;
}

// ---------------------------------------------------------------------------
// HMMA bf16-split GEMM.  Tile 128x128, BK=64, 8 warps (4m x 2n), warp 32x64.
// MODE 0 (layer1): C = relu(A@B + bias); write split bf16 to g_Hh/g_Hl [M][512]
// MODE 1 (layer2): bn==0 -> P (no bias); bn==128 -> OUT (+b2). fp32 [M][128].
// ---------------------------------------------------------------------------
#define GSMEM (2 * 65536)   // double buffer: (Ah,Al,Bh,Bl) x 16KB each

template <int MODE>
__global__ void __launch_bounds__(256, 1)
gemm_mma(const __nv_bfloat16* __restrict__ Ah, const __nv_bfloat16* __restrict__ Al,
         const __nv_bfloat16* __restrict__ Bh, const __nv_bfloat16* __restrict__ Bl,
         const float* __restrict__ bias,       // MODE0: b1 (len 512)
         __nv_bfloat16* __restrict__ Hh, __nv_bfloat16* __restrict__ Hl,
         float* __restrict__ P, float* __restrict__ OUT,
         const float* __restrict__ b2, int M) {
    extern __shared__ char smem_raw[];
    const uint32_t sb = smem_u32(smem_raw);
    const int tid  = threadIdx.x;
    const int lane = tid & 31;
    const int w    = tid >> 5;
    const int wm   = w & 3;          // 4 m-blocks of 32
    const int wn   = w >> 2;         // 2 n-blocks of 64
    const int bm   = blockIdx.y * 128;
    const int bn   = blockIdx.x * 128;
    constexpr int T = KCAT / 64;     // 8

    float acc[2][8][4];
#pragma unroll
    for (int i = 0; i < 2; ++i)
#pragma unroll
        for (int j = 0; j < 8; ++j)
#pragma unroll
            for (int c = 0; c < 4; ++c) acc[i][j][c] = 0.f;

    // ---- tile loader (cp.async 16B chunks, swizzled) ----
    auto load_tile = [&](int t, int s) {
        const int kk = t * 64;
        const uint32_t b0 = sb + s * 65536;
        const uint32_t dAh = b0, dAl = b0 + 16384, dBh = b0 + 32768, dBl = b0 + 49152;
#pragma unroll
        for (int i = 0; i < 4; ++i) {                 // A: 1024 chunks (128 rows x 8)
            int idx = tid + i * 256;
            int row = idx >> 3, c = idx & 7;
            int gm = bm + row;
            uint32_t off = swz(row * 128 + c * 16);
            int sz = (gm < M) ? 16 : 0;
            const char* pa = (const char*)(Ah + (size_t)gm * KCAT + kk + c * 8);
            const char* pl = (const char*)(Al + (size_t)gm * KCAT + kk + c * 8);
            CP_ASYNC16(dAh + off, pa, sz);
            CP_ASYNC16(dAl + off, pl, sz);
        }
#pragma unroll
        for (int i = 0; i < 4; ++i) {                 // B: 1024 chunks (128 n-rows x 8)
            int idx = tid + i * 256;
            int row = idx >> 3, c = idx & 7;
            int gn = bn + row;
            uint32_t off = swz(row * 128 + c * 16);
            const char* pb = (const char*)(Bh + (size_t)gn * KCAT + kk + c * 8);
            const char* pl = (const char*)(Bl + (size_t)gn * KCAT + kk + c * 8);
            CP_ASYNC16(dBh + off, pb, 16);
            CP_ASYNC16(dBl + off, pl, 16);
        }
    };

    const int lr16 = lane & 15;
    const int lc8  = (lane >> 4) * 8;

    auto compute = [&](int s) {
        const uint32_t b0 = sb + s * 65536;
        const uint32_t aH = b0, aL = b0 + 16384, bH = b0 + 32768, bL = b0 + 49152;
#pragma unroll
        for (int ks = 0; ks < 4; ++ks) {
            const int k0 = ks * 16;
            uint32_t ah[2][4], al[2][4];
#pragma unroll
            for (int i = 0; i < 2; ++i) {
                uint32_t off = swz((uint32_t)((wm * 32 + i * 16 + lr16) * 128 + (k0 + lc8) * 2));
                LDSM_X4(ah[i][0], ah[i][1], ah[i][2], ah[i][3], aH + off);
                LDSM_X4(al[i][0], al[i][1], al[i][2], al[i][3], aL + off);
            }
            uint32_t bh[8][2], bl[8][2];
#pragma unroll
            for (int jp = 0; jp < 4; ++jp) {
                uint32_t off = swz((uint32_t)((wn * 64 + jp * 16 + lr16) * 128 + (k0 + lc8) * 2));
                uint32_t q0, q1, q2, q3;
                LDSM_X4(q0, q1, q2, q3, bH + off);
                bh[2 * jp][0] = q0; bh[2 * jp][1] = q2;
                bh[2 * jp + 1][0] = q1; bh[2 * jp + 1][1] = q3;
                LDSM_X4(q0, q1, q2, q3, bL + off);
                bl[2 * jp][0] = q0; bl[2 * jp][1] = q2;
                bl[2 * jp + 1][0] = q1; bl[2 * jp + 1][1] = q3;
            }
#pragma unroll
            for (int i = 0; i < 2; ++i)
#pragma unroll
                for (int j = 0; j < 8; ++j) {
                    mma16816(acc[i][j], ah[i][0], ah[i][1], ah[i][2], ah[i][3],
                             bh[j][0], bh[j][1]);
                    mma16816(acc[i][j], ah[i][0], ah[i][1], ah[i][2], ah[i][3],
                             bl[j][0], bl[j][1]);
                    mma16816(acc[i][j], al[i][0], al[i][1], al[i][2], al[i][3],
                             bh[j][0], bh[j][1]);
                }
        }
    };

    load_tile(0, 0);
    CP_COMMIT();
    for (int t = 0; t < T; ++t) {
        const int s = t & 1;
        CP_WAIT0();
        __syncthreads();
        if (t + 1 < T) { load_tile(t + 1, s ^ 1); CP_COMMIT(); }
        compute(s);
        __syncthreads();
    }

    // ---- epilogue ----
    if (MODE == 0) {
#pragma unroll
        for (int i = 0; i < 2; ++i) {
            const int m0 = bm + wm * 32 + i * 16 + (lane >> 2);
#pragma unroll
            for (int j = 0; j < 8; ++j) {
                const int n = bn + wn * 64 + j * 8 + (lane & 3) * 2;
                float2 bb = *(const float2*)(bias + n);
                float v0 = fmaxf(acc[i][j][0] + bb.x, 0.f);
                float v1 = fmaxf(acc[i][j][1] + bb.y, 0.f);
                float v2 = fmaxf(acc[i][j][2] + bb.x, 0.f);
                float v3 = fmaxf(acc[i][j][3] + bb.y, 0.f);
                uint32_t h2, l2;
                if (m0 < M) {
                    split2(v0, v1, h2, l2);
                    *(uint32_t*)(Hh + (size_t)m0 * KCAT + n) = h2;
                    *(uint32_t*)(Hl + (size_t)m0 * KCAT + n) = l2;
                }
                if (m0 + 8 < M) {
                    split2(v2, v3, h2, l2);
                    *(uint32_t*)(Hh + (size_t)(m0 + 8) * KCAT + n) = h2;
                    *(uint32_t*)(Hl + (size_t)(m0 + 8) * KCAT + n) = l2;
                }
            }
        }
    } else {
        float* Csel = (bn == 0) ? P : OUT;
        const float* bsel = (bn == 0) ? (const float*)nullptr : b2;
#pragma unroll
        for (int i = 0; i < 2; ++i) {
            const int m0 = bm + wm * 32 + i * 16 + (lane >> 2);
#pragma unroll
            for (int j = 0; j < 8; ++j) {
                const int n = wn * 64 + j * 8 + (lane & 3) * 2;   // local col
                float bx = 0.f, by = 0.f;
                if (bsel) { float2 bb = *(const float2*)(bsel + n); bx = bb.x; by = bb.y; }
                if (m0 < M) {
                    float2 o = make_float2(acc[i][j][0] + bx, acc[i][j][1] + by);
                    *(float2*)(Csel + (size_t)m0 * C_OUT + n) = o;
                }
                if (m0 + 8 < M) {
                    float2 o = make_float2(acc[i][j][2] + bx, acc[i][j][3] + by);
                    *(float2*)(Csel + (size_t)(m0 + 8) * C_OUT + n) = o;
                }
            }
        }
    }
}

// ---------------------------------------------------------------------------
extern "C" void kernel_launch(void* const* d_in, const int* in_sizes, int n_in,
                              void* d_out, int out_size) {
    const float* x   = (const float*)d_in[0];
    const void*  ei  = d_in[1];
    const float* W1l = (const float*)d_in[2];
    const float* b1  = (const float*)d_in[3];
    const float* W1r = (const float*)d_in[4];
    const float* W2l = (const float*)d_in[5];
    const float* b2  = (const float*)d_in[6];
    const float* W2r = (const float*)d_in[7];
    float*       out = (float*)d_out;

    const int M = in_sizes[0] / F_IN;    // 10000
    const int E = in_sizes[1] / 2;       // 320000

    float *agg1, *P;
    __nv_bfloat16 *A1h, *A1l, *Hh, *Hl, *B1h, *B1l, *B2h, *B2l;
    cudaGetSymbolAddress((void**)&agg1, g_agg1);
    cudaGetSymbolAddress((void**)&P,    g_P);
    cudaGetSymbolAddress((void**)&A1h,  g_A1h);
    cudaGetSymbolAddress((void**)&A1l,  g_A1l);
    cudaGetSymbolAddress((void**)&Hh,   g_Hh);
    cudaGetSymbolAddress((void**)&Hl,   g_Hl);
    cudaGetSymbolAddress((void**)&B1h,  g_B1h);
    cudaGetSymbolAddress((void**)&B1l,  g_B1l);
    cudaGetSymbolAddress((void**)&B2h,  g_B2h);
    cudaGetSymbolAddress((void**)&B2l,  g_B2l);

    static int smem_set = 0;
    if (!smem_set) {
        cudaFuncSetAttribute(gemm_mma<0>, cudaFuncAttributeMaxDynamicSharedMemorySize, GSMEM);
        cudaFuncSetAttribute(gemm_mma<1>, cudaFuncAttributeMaxDynamicSharedMemorySize, GSMEM);
        smem_set = 1;
    }

    // ---- CSR build ----
    detect_dtype<<<1, 256>>>((const int*)ei, (2 * E < 2048) ? 2 * E : 2048);
    zero_deg<<<(NNODES + 255) / 256, 256>>>();
    convert_edges_hist<<<(E + 255) / 256, 256>>>(ei, E);
    build_rowptr<<<1, 1024>>>();
    fill_csr<<<(E + 255) / 256, 256>>>(E);

    // ---- weight pre-conversion (independent of edges) ----
    build_Bt1<<<(512 * 256 + 255) / 256, 256>>>(W1l, W1r);
    build_Bt2<<<(256 * 256 + 255) / 256, 256>>>(W2l, W2r);

    // ---- Layer 1: agg1 = segsum(x); A1 = [agg1|x] split;
    //      h(split) = relu(A1 @ [W1l;W1r] + b1) ----
    gather_rows<2, false><<<(M * 32 + 255) / 256, 256>>>(x, agg1, M);
    build_A1<<<(M * 256 + 255) / 256, 256>>>(x, M);
    {
        dim3 grid(HID / 128, (M + 127) / 128);   // (4, 79)
        gemm_mma<0><<<grid, 256, GSMEM>>>(A1h, A1l, B1h, B1l, b1,
                                          Hh, Hl, nullptr, nullptr, nullptr, M);
    }

    // ---- Layer 2 (linearity reorder): [P|out] = h @ [W2l|W2r] (+b2 on out);
    //      out += segsum(P) ----
    {
        dim3 grid(2 * C_OUT / 128, (M + 127) / 128);  // (2, 79)
        gemm_mma<1><<<grid, 256, GSMEM>>>(Hh, Hl, B2h, B2l, nullptr,
                                          nullptr, nullptr, P, out, b2, M);
    }
    gather_rows<1, true><<<(M * 32 + 255) / 256, 256>>>(P, out, M);
}

// round 9
// speedup vs baseline: 2.8224x; 1.2181x over previous
#include <cuda_runtime.h>
#include <cuda_bf16.h>
#include <cstdint>

#define NNODES 10000
#define F_IN   256
#define HID    512
#define C_OUT  128
#define NEDGES 320000
#define KCAT   512            // K for both fused GEMMs

// ---------------------------------------------------------------------------
// Scratch (allocation-free rule: __device__ globals)
// ---------------------------------------------------------------------------
__device__ __align__(1024) float g_P   [NNODES * C_OUT];         // h @ W2l fp32
__device__ __align__(1024) __nv_bfloat16 g_A1h[NNODES * KCAT];   // [agg1|x] hi
__device__ __align__(1024) __nv_bfloat16 g_A1l[NNODES * KCAT];   // [agg1|x] lo
__device__ __align__(1024) __nv_bfloat16 g_Hh [NNODES * KCAT];   // h hi
__device__ __align__(1024) __nv_bfloat16 g_Hl [NNODES * KCAT];   // h lo
__device__ __align__(1024) __nv_bfloat16 g_B1h[HID * KCAT];      // [W1l;W1r]^T hi  [N=512][K=512]
__device__ __align__(1024) __nv_bfloat16 g_B1l[HID * KCAT];
__device__ __align__(1024) __nv_bfloat16 g_B2h[(2 * C_OUT) * KCAT]; // [W2l|W2r]^T hi [N=256][K=512]
__device__ __align__(1024) __nv_bfloat16 g_B2l[(2 * C_OUT) * KCAT];
__device__ int g_src[NEDGES];
__device__ int g_dst[NEDGES];
__device__ int g_deg[NNODES];
__device__ int g_rowptr[NNODES + 1];
__device__ int g_cursor[NNODES];
__device__ int g_csr[NEDGES];
__device__ int g_is32;

// ---------------------------------------------------------------------------
// PTX helpers (plain sm_80+ PTX; NO sm_103a-only features — harness targets sm_103)
// ---------------------------------------------------------------------------
__device__ __forceinline__ uint32_t smem_u32(const void* p) {
    uint32_t a;
    asm("{ .reg .u64 t; cvta.to.shared.u64 t, %1; cvt.u32.u64 %0, t; }"
        : "=r"(a) : "l"(p));
    return a;
}
#define CP_ASYNC16(dst, src, sz) \
    asm volatile("cp.async.cg.shared.global [%0], [%1], 16, %2;" \
                 :: "r"(dst), "l"(src), "r"(sz) : "memory")
#define CP_COMMIT() asm volatile("cp.async.commit_group;" ::: "memory")
#define CP_WAIT0()  asm volatile("cp.async.wait_group 0;" ::: "memory")
#define LDSM_X4(r0, r1, r2, r3, addr) \
    asm volatile("ldmatrix.sync.aligned.m8n8.x4.shared.b16 {%0,%1,%2,%3}, [%4];" \
                 : "=r"(r0), "=r"(r1), "=r"(r2), "=r"(r3) : "r"(addr))

__device__ __forceinline__ void mma16816(float c[4],
                                         uint32_t a0, uint32_t a1, uint32_t a2, uint32_t a3,
                                         uint32_t b0, uint32_t b1) {
    asm volatile(
        "mma.sync.aligned.m16n8k16.row.col.f32.bf16.bf16.f32 "
        "{%0,%1,%2,%3}, {%4,%5,%6,%7}, {%8,%9}, {%0,%1,%2,%3};"
        : "+f"(c[0]), "+f"(c[1]), "+f"(c[2]), "+f"(c[3])
        : "r"(a0), "r"(a1), "r"(a2), "r"(a3), "r"(b0), "r"(b1));
}

__device__ __forceinline__ uint32_t swz(uint32_t off) {   // SW128-style XOR
    return off ^ ((off >> 3) & 0x70);
}

__device__ __forceinline__ void split2(float a, float b, uint32_t& h2o, uint32_t& l2o) {
    __nv_bfloat162 hv, lv;
    hv.x = __float2bfloat16(a);
    hv.y = __float2bfloat16(b);
    lv.x = __float2bfloat16(a - __bfloat162float(hv.x));
    lv.y = __float2bfloat16(b - __bfloat162float(hv.y));
    h2o = *reinterpret_cast<uint32_t*>(&hv);
    l2o = *reinterpret_cast<uint32_t*>(&lv);
}

// ---------------------------------------------------------------------------
// Edge decode + CSR build
// ---------------------------------------------------------------------------
// Detect dtype AND zero the degree histogram (merged launch).
__global__ void detect_and_zero(const int* __restrict__ ei32, int n_check) {
    __shared__ int s_any;
    if (threadIdx.x == 0) s_any = 0;
    __syncthreads();
    int any = 0;
    for (int i = 2 * threadIdx.x + 1; i < n_check; i += 2 * blockDim.x)
        any |= ei32[i];
    if (any) atomicOr(&s_any, 1);
    for (int i = threadIdx.x; i < NNODES; i += blockDim.x) g_deg[i] = 0;
    __syncthreads();
    if (threadIdx.x == 0) g_is32 = (s_any != 0) ? 1 : 0;
}

__global__ void convert_edges_hist(const void* __restrict__ ei, int E) {
    const int is32 = g_is32;
    int e = blockIdx.x * blockDim.x + threadIdx.x;
    int stride = gridDim.x * blockDim.x;
    for (; e < E; e += stride) {
        long long s, d;
        if (is32) {
            const int* p = (const int*)ei;
            s = p[e]; d = p[E + e];
        } else {
            const long long* p = (const long long*)ei;
            s = p[e]; d = p[E + e];
        }
        if (s < 0) s = 0; if (s >= NNODES) s = NNODES - 1;
        if (d < 0) d = 0; if (d >= NNODES) d = NNODES - 1;
        g_src[e] = (int)s;
        g_dst[e] = (int)d;
        atomicAdd(&g_deg[(int)d], 1);
    }
}

// Exclusive scan of g_deg -> g_rowptr/g_cursor. All gmem traffic coalesced
// via smem staging (the R8 version was fully uncoalesced: 17us for 40KB).
__global__ void build_rowptr() {
    __shared__ int sdeg[NNODES];      // 40 KB
    __shared__ int wsum[32];
    const int t = threadIdx.x;
    const int lane = t & 31, w = t >> 5;

    for (int i = t; i < NNODES; i += 1024) sdeg[i] = g_deg[i];  // coalesced LDG
    __syncthreads();

    const int base = t * 16;
    int local[16];
    int s = 0;
#pragma unroll
    for (int i = 0; i < 16; ++i) {
        int idx = base + i;
        int v = (idx < NNODES) ? sdeg[idx] : 0;
        local[i] = s; s += v;
    }
    int inc = s;
#pragma unroll
    for (int o = 1; o < 32; o <<= 1) {
        int v = __shfl_up_sync(0xffffffffu, inc, o);
        if (lane >= o) inc += v;
    }
    if (lane == 31) wsum[w] = inc;
    __syncthreads();
    if (w == 0) {
        int v2 = wsum[lane];
#pragma unroll
        for (int o = 1; o < 32; o <<= 1) {
            int u = __shfl_up_sync(0xffffffffu, v2, o);
            if (lane >= o) v2 += u;
        }
        wsum[lane] = v2;
    }
    __syncthreads();
    int excl = inc - s + (w ? wsum[w - 1] : 0);
#pragma unroll
    for (int i = 0; i < 16; ++i) {
        int idx = base + i;
        if (idx < NNODES) sdeg[idx] = excl + local[i];   // stage result in smem
    }
    __syncthreads();
    for (int i = t; i < NNODES; i += 1024) {             // coalesced STG x2
        int v = sdeg[i];
        g_rowptr[i] = v;
        g_cursor[i] = v;
    }
    if (t == 1023) g_rowptr[NNODES] = wsum[31];
}

__global__ void fill_csr(int E) {
    int e = blockIdx.x * blockDim.x + threadIdx.x;
    int stride = gridDim.x * blockDim.x;
    for (; e < E; e += stride) {
        int d = g_dst[e];
        int pos = atomicAdd(&g_cursor[d], 1);
        g_csr[pos] = g_src[e];
    }
}

// ---------------------------------------------------------------------------
// Layer-1 gather fused with bf16 split: A1[:, 0:256] = split(segsum(x)).
// Warp per destination node, F=256.
// ---------------------------------------------------------------------------
__global__ void gather_splitA(const float* __restrict__ X, int Nn) {
    int node = (blockIdx.x * blockDim.x + threadIdx.x) >> 5;
    if (node >= Nn) return;
    int lane = threadIdx.x & 31;
    int r0 = g_rowptr[node];
    int r1 = g_rowptr[node + 1];

    float4 acc[2];
    acc[0] = make_float4(0.f, 0.f, 0.f, 0.f);
    acc[1] = make_float4(0.f, 0.f, 0.f, 0.f);

    int e = r0;
    for (; e + 1 < r1; e += 2) {
        const float4* p0 = (const float4*)(X + (size_t)g_csr[e] * F_IN);
        const float4* p1 = (const float4*)(X + (size_t)g_csr[e + 1] * F_IN);
#pragma unroll
        for (int j = 0; j < 2; ++j) {
            float4 a = p0[lane + 32 * j];
            float4 b = p1[lane + 32 * j];
            acc[j].x += a.x + b.x;
            acc[j].y += a.y + b.y;
            acc[j].z += a.z + b.z;
            acc[j].w += a.w + b.w;
        }
    }
    if (e < r1) {
        const float4* p0 = (const float4*)(X + (size_t)g_csr[e] * F_IN);
#pragma unroll
        for (int j = 0; j < 2; ++j) {
            float4 a = p0[lane + 32 * j];
            acc[j].x += a.x; acc[j].y += a.y;
            acc[j].z += a.z; acc[j].w += a.w;
        }
    }

#pragma unroll
    for (int j = 0; j < 2; ++j) {
        int col = (lane + 32 * j) * 4;
        uint32_t h0, l0, h1, l1;
        split2(acc[j].x, acc[j].y, h0, l0);
        split2(acc[j].z, acc[j].w, h1, l1);
        *(uint2*)(g_A1h + (size_t)node * KCAT + col) = make_uint2(h0, h1);
        *(uint2*)(g_A1l + (size_t)node * KCAT + col) = make_uint2(l0, l1);
    }
}

// P-gather: out[node] += segsum(P), F=128, fp32.
__global__ void gather_P(const float* __restrict__ X, float* __restrict__ OUT, int Nn) {
    int node = (blockIdx.x * blockDim.x + threadIdx.x) >> 5;
    if (node >= Nn) return;
    int lane = threadIdx.x & 31;
    int r0 = g_rowptr[node];
    int r1 = g_rowptr[node + 1];

    float4 acc = ((const float4*)(OUT + (size_t)node * C_OUT))[lane];
    int e = r0;
    for (; e + 1 < r1; e += 2) {
        float4 a = ((const float4*)(X + (size_t)g_csr[e] * C_OUT))[lane];
        float4 b = ((const float4*)(X + (size_t)g_csr[e + 1] * C_OUT))[lane];
        acc.x += a.x + b.x; acc.y += a.y + b.y;
        acc.z += a.z + b.z; acc.w += a.w + b.w;
    }
    if (e < r1) {
        float4 a = ((const float4*)(X + (size_t)g_csr[e] * C_OUT))[lane];
        acc.x += a.x; acc.y += a.y; acc.z += a.z; acc.w += a.w;
    }
    ((float4*)(OUT + (size_t)node * C_OUT))[lane] = acc;
}

// ---------------------------------------------------------------------------
// Pre-conversion kernels
// ---------------------------------------------------------------------------
__global__ void convert_x(const float* __restrict__ x, int M) {
    // A1[:, 256:512] = split(x)
    int p = blockIdx.x * blockDim.x + threadIdx.x;
    if (p >= M * 128) return;
    int m = p >> 7;
    int c2 = (p & 127) * 2;
    float a = x[m * 256 + c2];
    float b = x[m * 256 + c2 + 1];
    uint32_t h2, l2;
    split2(a, b, h2, l2);
    *(uint32_t*)(g_A1h + (size_t)m * KCAT + 256 + c2) = h2;
    *(uint32_t*)(g_A1l + (size_t)m * KCAT + 256 + c2) = l2;
}

__global__ void build_Bt1(const float* __restrict__ W1l, const float* __restrict__ W1r) {
    // g_B1h/l[n][k]: k<256 ? W1l[k][n] : W1r[k-256][n]
    int p = blockIdx.x * blockDim.x + threadIdx.x;
    if (p >= 512 * 256) return;
    int n = p >> 8;
    int k = (p & 255) * 2;
    float a, b;
    if (k < 256) { a = W1l[k * 512 + n]; b = W1l[(k + 1) * 512 + n]; }
    else         { a = W1r[(k - 256) * 512 + n]; b = W1r[(k - 255) * 512 + n]; }
    uint32_t h2, l2;
    split2(a, b, h2, l2);
    *(uint32_t*)(g_B1h + (size_t)n * KCAT + k) = h2;
    *(uint32_t*)(g_B1l + (size_t)n * KCAT + k) = l2;
}

__global__ void build_Bt2(const float* __restrict__ W2l, const float* __restrict__ W2r) {
    // g_B2h/l[n][k]: n<128 ? W2l[k][n] : W2r[k][n-128]
    int p = blockIdx.x * blockDim.x + threadIdx.x;
    if (p >= 256 * 256) return;
    int n = p >> 8;
    int k = (p & 255) * 2;
    const float* W = (n < 128) ? W2l : W2r;
    int nn = n & 127;
    float a = W[k * 128 + nn];
    float b = W[(k + 1) * 128 + nn];
    uint32_t h2, l2;
    split2(a, b, h2, l2);
    *(uint32_t*)(g_B2h + (size_t)n * KCAT + k) = h2;
    *(uint32_t*)(g_B2l + (size_t)n * KCAT + k) = l2;
}

// ---------------------------------------------------------------------------
// HMMA bf16-split GEMM.  Tile 128x64, BK=64, 8 warps (4m x 2n), warp 32x32.
// 96KB smem double buffer -> 2 CTAs/SM.
// MODE 0 (layer1): C = relu(A@B + bias); write split bf16 to Hh/Hl [M][512]
// MODE 1 (layer2): cols <128 -> P (no bias); cols >=128 -> OUT (+b2).
// ---------------------------------------------------------------------------
#define STAGE_BYTES 49152
#define GSMEM (2 * STAGE_BYTES)   // Ah16K, Al16K, Bh8K, Bl8K per stage

template <int MODE>
__global__ void __launch_bounds__(256, 2)
gemm_mma(const __nv_bfloat16* __restrict__ Ah, const __nv_bfloat16* __restrict__ Al,
         const __nv_bfloat16* __restrict__ Bh, const __nv_bfloat16* __restrict__ Bl,
         const float* __restrict__ bias,       // MODE0: b1
         __nv_bfloat16* __restrict__ Hh, __nv_bfloat16* __restrict__ Hl,
         float* __restrict__ P, float* __restrict__ OUT,
         const float* __restrict__ b2, int M) {
    extern __shared__ char smem_raw[];
    const uint32_t sb = smem_u32(smem_raw);
    const int tid  = threadIdx.x;
    const int lane = tid & 31;
    const int w    = tid >> 5;
    const int wm   = w & 3;          // 4 m-blocks of 32
    const int wn   = w >> 2;         // 2 n-blocks of 32
    const int bm   = blockIdx.y * 128;
    const int bn   = blockIdx.x * 64;
    constexpr int T = KCAT / 64;     // 8

    float acc[2][4][4];
#pragma unroll
    for (int i = 0; i < 2; ++i)
#pragma unroll
        for (int j = 0; j < 4; ++j)
#pragma unroll
            for (int c = 0; c < 4; ++c) acc[i][j][c] = 0.f;

    auto load_tile = [&](int t, int s) {
        const int kk = t * 64;
        const uint32_t b0 = sb + s * STAGE_BYTES;
        const uint32_t dAh = b0, dAl = b0 + 16384, dBh = b0 + 32768, dBl = b0 + 40960;
#pragma unroll
        for (int i = 0; i < 4; ++i) {                 // A: 1024 chunks (128 rows x 8)
            int idx = tid + i * 256;
            int row = idx >> 3, c = idx & 7;
            int gm = bm + row;
            uint32_t off = swz(row * 128 + c * 16);
            int sz = (gm < M) ? 16 : 0;
            const char* pa = (const char*)(Ah + (size_t)gm * KCAT + kk + c * 8);
            const char* pl = (const char*)(Al + (size_t)gm * KCAT + kk + c * 8);
            CP_ASYNC16(dAh + off, pa, sz);
            CP_ASYNC16(dAl + off, pl, sz);
        }
#pragma unroll
        for (int i = 0; i < 2; ++i) {                 // B: 512 chunks (64 n-rows x 8)
            int idx = tid + i * 256;
            int row = idx >> 3, c = idx & 7;
            int gn = bn + row;
            uint32_t off = swz(row * 128 + c * 16);
            const char* pb = (const char*)(Bh + (size_t)gn * KCAT + kk + c * 8);
            const char* pl = (const char*)(Bl + (size_t)gn * KCAT + kk + c * 8);
            CP_ASYNC16(dBh + off, pb, 16);
            CP_ASYNC16(dBl + off, pl, 16);
        }
    };

    const int lr16 = lane & 15;
    const int lc8  = (lane >> 4) * 8;

    auto compute = [&](int s) {
        const uint32_t b0 = sb + s * STAGE_BYTES;
        const uint32_t aH = b0, aL = b0 + 16384, bH = b0 + 32768, bL = b0 + 40960;
#pragma unroll
        for (int ks = 0; ks < 4; ++ks) {
            const int k0 = ks * 16;
            uint32_t ah[2][4], al[2][4];
#pragma unroll
            for (int i = 0; i < 2; ++i) {
                uint32_t off = swz((uint32_t)((wm * 32 + i * 16 + lr16) * 128 + (k0 + lc8) * 2));
                LDSM_X4(ah[i][0], ah[i][1], ah[i][2], ah[i][3], aH + off);
                LDSM_X4(al[i][0], al[i][1], al[i][2], al[i][3], aL + off);
            }
            uint32_t bh[4][2], bl[4][2];
#pragma unroll
            for (int jp = 0; jp < 2; ++jp) {
                uint32_t off = swz((uint32_t)((wn * 32 + jp * 16 + lr16) * 128 + (k0 + lc8) * 2));
                uint32_t q0, q1, q2, q3;
                LDSM_X4(q0, q1, q2, q3, bH + off);
                bh[2 * jp][0] = q0; bh[2 * jp][1] = q2;
                bh[2 * jp + 1][0] = q1; bh[2 * jp + 1][1] = q3;
                LDSM_X4(q0, q1, q2, q3, bL + off);
                bl[2 * jp][0] = q0; bl[2 * jp][1] = q2;
                bl[2 * jp + 1][0] = q1; bl[2 * jp + 1][1] = q3;
            }
#pragma unroll
            for (int i = 0; i < 2; ++i)
#pragma unroll
                for (int j = 0; j < 4; ++j) {
                    mma16816(acc[i][j], ah[i][0], ah[i][1], ah[i][2], ah[i][3],
                             bh[j][0], bh[j][1]);
                    mma16816(acc[i][j], ah[i][0], ah[i][1], ah[i][2], ah[i][3],
                             bl[j][0], bl[j][1]);
                    mma16816(acc[i][j], al[i][0], al[i][1], al[i][2], al[i][3],
                             bh[j][0], bh[j][1]);
                }
        }
    };

    load_tile(0, 0);
    CP_COMMIT();
    for (int t = 0; t < T; ++t) {
        const int s = t & 1;
        CP_WAIT0();
        __syncthreads();
        if (t + 1 < T) { load_tile(t + 1, s ^ 1); CP_COMMIT(); }
        compute(s);
        __syncthreads();
    }

    // ---- epilogue ----
#pragma unroll
    for (int i = 0; i < 2; ++i) {
        const int m0 = bm + wm * 32 + i * 16 + (lane >> 2);
#pragma unroll
        for (int j = 0; j < 4; ++j) {
            const int n = bn + wn * 32 + j * 8 + (lane & 3) * 2;
            if (MODE == 0) {
                float2 bb = *(const float2*)(bias + n);
                float v0 = fmaxf(acc[i][j][0] + bb.x, 0.f);
                float v1 = fmaxf(acc[i][j][1] + bb.y, 0.f);
                float v2 = fmaxf(acc[i][j][2] + bb.x, 0.f);
                float v3 = fmaxf(acc[i][j][3] + bb.y, 0.f);
                uint32_t h2, l2;
                if (m0 < M) {
                    split2(v0, v1, h2, l2);
                    *(uint32_t*)(Hh + (size_t)m0 * KCAT + n) = h2;
                    *(uint32_t*)(Hl + (size_t)m0 * KCAT + n) = l2;
                }
                if (m0 + 8 < M) {
                    split2(v2, v3, h2, l2);
                    *(uint32_t*)(Hh + (size_t)(m0 + 8) * KCAT + n) = h2;
                    *(uint32_t*)(Hl + (size_t)(m0 + 8) * KCAT + n) = l2;
                }
            } else {
                float* Csel = (n < 128) ? P : OUT;
                const int cn = (n < 128) ? n : (n - 128);
                float bx = 0.f, by = 0.f;
                if (n >= 128) { float2 bb = *(const float2*)(b2 + cn); bx = bb.x; by = bb.y; }
                if (m0 < M)
                    *(float2*)(Csel + (size_t)m0 * C_OUT + cn) =
                        make_float2(acc[i][j][0] + bx, acc[i][j][1] + by);
                if (m0 + 8 < M)
                    *(float2*)(Csel + (size_t)(m0 + 8) * C_OUT + cn) =
                        make_float2(acc[i][j][2] + bx, acc[i][j][3] + by);
            }
        }
    }
}

// ---------------------------------------------------------------------------
extern "C" void kernel_launch(void* const* d_in, const int* in_sizes, int n_in,
                              void* d_out, int out_size) {
    const float* x   = (const float*)d_in[0];
    const void*  ei  = d_in[1];
    const float* W1l = (const float*)d_in[2];
    const float* b1  = (const float*)d_in[3];
    const float* W1r = (const float*)d_in[4];
    const float* W2l = (const float*)d_in[5];
    const float* b2  = (const float*)d_in[6];
    const float* W2r = (const float*)d_in[7];
    float*       out = (float*)d_out;

    const int M = in_sizes[0] / F_IN;    // 10000
    const int E = in_sizes[1] / 2;       // 320000

    float* P;
    __nv_bfloat16 *A1h, *A1l, *Hh, *Hl, *B1h, *B1l, *B2h, *B2l;
    cudaGetSymbolAddress((void**)&P,   g_P);
    cudaGetSymbolAddress((void**)&A1h, g_A1h);
    cudaGetSymbolAddress((void**)&A1l, g_A1l);
    cudaGetSymbolAddress((void**)&Hh,  g_Hh);
    cudaGetSymbolAddress((void**)&Hl,  g_Hl);
    cudaGetSymbolAddress((void**)&B1h, g_B1h);
    cudaGetSymbolAddress((void**)&B1l, g_B1l);
    cudaGetSymbolAddress((void**)&B2h, g_B2h);
    cudaGetSymbolAddress((void**)&B2l, g_B2l);

    static int smem_set = 0;
    if (!smem_set) {
        cudaFuncSetAttribute(gemm_mma<0>, cudaFuncAttributeMaxDynamicSharedMemorySize, GSMEM);
        cudaFuncSetAttribute(gemm_mma<1>, cudaFuncAttributeMaxDynamicSharedMemorySize, GSMEM);
        smem_set = 1;
    }

    // ---- CSR build ----
    detect_and_zero<<<1, 256>>>((const int*)ei, (2 * E < 2048) ? 2 * E : 2048);
    convert_edges_hist<<<(E + 255) / 256, 256>>>(ei, E);
    build_rowptr<<<1, 1024>>>();
    fill_csr<<<(E + 255) / 256, 256>>>(E);

    // ---- input/weight pre-conversion ----
    convert_x<<<(M * 128 + 255) / 256, 256>>>(x, M);
    build_Bt1<<<(512 * 256 + 255) / 256, 256>>>(W1l, W1r);
    build_Bt2<<<(256 * 256 + 255) / 256, 256>>>(W2l, W2r);

    // ---- Layer 1: A1[:,0:256] = split(segsum(x)) (fused);
    //      h(split) = relu(A1 @ [W1l;W1r] + b1) ----
    gather_splitA<<<(M * 32 + 255) / 256, 256>>>(x, M);
    {
        dim3 grid(HID / 64, (M + 127) / 128);   // (8, 79)
        gemm_mma<0><<<grid, 256, GSMEM>>>(A1h, A1l, B1h, B1l, b1,
                                          Hh, Hl, nullptr, nullptr, nullptr, M);
    }

    // ---- Layer 2 (linearity reorder): [P|out] = h @ [W2l|W2r] (+b2 on out);
    //      out += segsum(P) ----
    {
        dim3 grid(2 * C_OUT / 64, (M + 127) / 128);  // (4, 79)
        gemm_mma<1><<<grid, 256, GSMEM>>>(Hh, Hl, B2h, B2l, nullptr,
                                          nullptr, nullptr, P, out, b2, M);
    }
    gather_P<<<(M * 32 + 255) / 256, 256>>>(P, out, M);
}

// round 11
// speedup vs baseline: 2.9352x; 1.0400x over previous
#include <cuda_runtime.h>
#include <cuda_bf16.h>
#include <cstdint>

#define NNODES 10000
#define F_IN   256
#define HID    512
#define C_OUT  128
#define NEDGES 320000
#define KCAT   512            // K for both fused GEMMs

// ---------------------------------------------------------------------------
// Scratch (allocation-free rule: __device__ globals)
// ---------------------------------------------------------------------------
__device__ __align__(1024) float g_P   [NNODES * C_OUT];         // h @ W2l fp32
__device__ __align__(1024) __nv_bfloat16 g_A1h[NNODES * KCAT];   // [agg1|x] hi
__device__ __align__(1024) __nv_bfloat16 g_A1l[NNODES * KCAT];   // [agg1|x] lo
__device__ __align__(1024) __nv_bfloat16 g_Hh [NNODES * KCAT];   // h hi
__device__ __align__(1024) __nv_bfloat16 g_Hl [NNODES * KCAT];   // h lo
__device__ __align__(1024) __nv_bfloat16 g_B1h[HID * KCAT];      // [W1l;W1r]^T hi [512][512]
__device__ __align__(1024) __nv_bfloat16 g_B1l[HID * KCAT];
__device__ __align__(1024) __nv_bfloat16 g_B2h[(2 * C_OUT) * KCAT]; // [W2l|W2r]^T hi [256][512]
__device__ __align__(1024) __nv_bfloat16 g_B2l[(2 * C_OUT) * KCAT];
__device__ int g_src[NEDGES];
__device__ int g_dst[NEDGES];
__device__ int g_seq[NEDGES];       // per-dest sequence number (from hist atomic)
__device__ int g_deg[NNODES];
__device__ int g_rowptr[NNODES + 1];
__device__ int g_csr[NEDGES];
__device__ int g_is32;

// ---------------------------------------------------------------------------
// PTX helpers (plain sm_80+ PTX; NO sm_103a-only features — harness targets sm_103)
// ---------------------------------------------------------------------------
__device__ __forceinline__ uint32_t smem_u32(const void* p) {
    uint32_t a;
    asm("{ .reg .u64 t; cvta.to.shared.u64 t, %1; cvt.u32.u64 %0, t; }"
        : "=r"(a) : "l"(p));
    return a;
}
#define CP_ASYNC16(dst, src, sz) \
    asm volatile("cp.async.cg.shared.global [%0], [%1], 16, %2;" \
                 :: "r"(dst), "l"(src), "r"(sz) : "memory")
#define CP_COMMIT() asm volatile("cp.async.commit_group;" ::: "memory")
#define CP_WAIT0()  asm volatile("cp.async.wait_group 0;" ::: "memory")
#define LDSM_X4(r0, r1, r2, r3, addr) \
    asm volatile("ldmatrix.sync.aligned.m8n8.x4.shared.b16 {%0,%1,%2,%3}, [%4];" \
                 : "=r"(r0), "=r"(r1), "=r"(r2), "=r"(r3) : "r"(addr))

__device__ __forceinline__ void mma16816(float c[4],
                                         uint32_t a0, uint32_t a1, uint32_t a2, uint32_t a3,
                                         uint32_t b0, uint32_t b1) {
    asm volatile(
        "mma.sync.aligned.m16n8k16.row.col.f32.bf16.bf16.f32 "
        "{%0,%1,%2,%3}, {%4,%5,%6,%7}, {%8,%9}, {%0,%1,%2,%3};"
        : "+f"(c[0]), "+f"(c[1]), "+f"(c[2]), "+f"(c[3])
        : "r"(a0), "r"(a1), "r"(a2), "r"(a3), "r"(b0), "r"(b1));
}

__device__ __forceinline__ uint32_t swz(uint32_t off) {   // SW128-style XOR
    return off ^ ((off >> 3) & 0x70);
}

__device__ __forceinline__ void split2(float a, float b, uint32_t& h2o, uint32_t& l2o) {
    __nv_bfloat162 hv, lv;
    hv.x = __float2bfloat16(a);
    hv.y = __float2bfloat16(b);
    lv.x = __float2bfloat16(a - __bfloat162float(hv.x));
    lv.y = __float2bfloat16(b - __bfloat162float(hv.y));
    h2o = *reinterpret_cast<uint32_t*>(&hv);
    l2o = *reinterpret_cast<uint32_t*>(&lv);
}

// ---------------------------------------------------------------------------
// Edge decode + CSR build
// ---------------------------------------------------------------------------
__global__ void detect_and_zero(const int* __restrict__ ei32, int n_check) {
    __shared__ int s_any;
    if (threadIdx.x == 0) s_any = 0;
    __syncthreads();
    int any = 0;
    for (int i = 2 * threadIdx.x + 1; i < n_check; i += 2 * blockDim.x)
        any |= ei32[i];
    if (any) atomicOr(&s_any, 1);
    for (int i = threadIdx.x; i < NNODES; i += blockDim.x) g_deg[i] = 0;
    __syncthreads();
    if (threadIdx.x == 0) g_is32 = (s_any != 0) ? 1 : 0;
}

// Materialize src/dst + degree histogram + per-dest sequence number in one pass.
__global__ void convert_edges_hist(const void* __restrict__ ei, int E) {
    const int is32 = g_is32;
    int e = blockIdx.x * blockDim.x + threadIdx.x;
    int stride = gridDim.x * blockDim.x;
    for (; e < E; e += stride) {
        long long s, d;
        if (is32) {
            const int* p = (const int*)ei;
            s = p[e]; d = p[E + e];
        } else {
            const long long* p = (const long long*)ei;
            s = p[e]; d = p[E + e];
        }
        if (s < 0) s = 0; if (s >= NNODES) s = NNODES - 1;
        if (d < 0) d = 0; if (d >= NNODES) d = NNODES - 1;
        g_src[e] = (int)s;
        g_dst[e] = (int)d;
        g_seq[e] = atomicAdd(&g_deg[(int)d], 1);
    }
}

// Exclusive scan of g_deg -> g_rowptr; gmem coalesced via smem staging.
__global__ void build_rowptr() {
    __shared__ int sdeg[NNODES];      // 40 KB
    __shared__ int wsum[32];
    const int t = threadIdx.x;
    const int lane = t & 31, w = t >> 5;

    for (int i = t; i < NNODES; i += 1024) sdeg[i] = g_deg[i];
    __syncthreads();

    const int base = t * 16;
    int local[16];
    int s = 0;
#pragma unroll
    for (int i = 0; i < 16; ++i) {
        int idx = base + i;
        int v = (idx < NNODES) ? sdeg[idx] : 0;
        local[i] = s; s += v;
    }
    int inc = s;
#pragma unroll
    for (int o = 1; o < 32; o <<= 1) {
        int v = __shfl_up_sync(0xffffffffu, inc, o);
        if (lane >= o) inc += v;
    }
    if (lane == 31) wsum[w] = inc;
    __syncthreads();
    if (w == 0) {
        int v2 = wsum[lane];
#pragma unroll
        for (int o = 1; o < 32; o <<= 1) {
            int u = __shfl_up_sync(0xffffffffu, v2, o);
            if (lane >= o) v2 += u;
        }
        wsum[lane] = v2;
    }
    __syncthreads();
    int excl = inc - s + (w ? wsum[w - 1] : 0);
#pragma unroll
    for (int i = 0; i < 16; ++i) {
        int idx = base + i;
        if (idx < NNODES) sdeg[idx] = excl + local[i];
    }
    __syncthreads();
    for (int i = t; i < NNODES; i += 1024) g_rowptr[i] = sdeg[i];
    if (t == 1023) g_rowptr[NNODES] = wsum[31];
}

// Atomic-free CSR fill: position = rowptr[dst] + seq (unique by construction).
__global__ void fill_csr(int E) {
    int e = blockIdx.x * blockDim.x + threadIdx.x;
    if (e < E) {
        int d = g_dst[e];
        g_csr[g_rowptr[d] + g_seq[e]] = g_src[e];
    }
}

// ---------------------------------------------------------------------------
// Layer-1 gather fused with bf16 split: A1[:, 0:256] = split(segsum(x)).
// ---------------------------------------------------------------------------
__global__ void gather_splitA(const float* __restrict__ X, int Nn) {
    int node = (blockIdx.x * blockDim.x + threadIdx.x) >> 5;
    if (node >= Nn) return;
    int lane = threadIdx.x & 31;
    int r0 = g_rowptr[node];
    int r1 = g_rowptr[node + 1];

    float4 acc[2];
    acc[0] = make_float4(0.f, 0.f, 0.f, 0.f);
    acc[1] = make_float4(0.f, 0.f, 0.f, 0.f);

    int e = r0;
    for (; e + 1 < r1; e += 2) {
        const float4* p0 = (const float4*)(X + (size_t)g_csr[e] * F_IN);
        const float4* p1 = (const float4*)(X + (size_t)g_csr[e + 1] * F_IN);
#pragma unroll
        for (int j = 0; j < 2; ++j) {
            float4 a = p0[lane + 32 * j];
            float4 b = p1[lane + 32 * j];
            acc[j].x += a.x + b.x;
            acc[j].y += a.y + b.y;
            acc[j].z += a.z + b.z;
            acc[j].w += a.w + b.w;
        }
    }
    if (e < r1) {
        const float4* p0 = (const float4*)(X + (size_t)g_csr[e] * F_IN);
#pragma unroll
        for (int j = 0; j < 2; ++j) {
            float4 a = p0[lane + 32 * j];
            acc[j].x += a.x; acc[j].y += a.y;
            acc[j].z += a.z; acc[j].w += a.w;
        }
    }

#pragma unroll
    for (int j = 0; j < 2; ++j) {
        int col = (lane + 32 * j) * 4;
        uint32_t h0, l0, h1, l1;
        split2(acc[j].x, acc[j].y, h0, l0);
        split2(acc[j].z, acc[j].w, h1, l1);
        *(uint2*)(g_A1h + (size_t)node * KCAT + col) = make_uint2(h0, h1);
        *(uint2*)(g_A1l + (size_t)node * KCAT + col) = make_uint2(l0, l1);
    }
}

// P-gather: out[node] += segsum(P), F=128, fp32.
__global__ void gather_P(const float* __restrict__ X, float* __restrict__ OUT, int Nn) {
    int node = (blockIdx.x * blockDim.x + threadIdx.x) >> 5;
    if (node >= Nn) return;
    int lane = threadIdx.x & 31;
    int r0 = g_rowptr[node];
    int r1 = g_rowptr[node + 1];

    float4 acc = ((const float4*)(OUT + (size_t)node * C_OUT))[lane];
    int e = r0;
    for (; e + 1 < r1; e += 2) {
        float4 a = ((const float4*)(X + (size_t)g_csr[e] * C_OUT))[lane];
        float4 b = ((const float4*)(X + (size_t)g_csr[e + 1] * C_OUT))[lane];
        acc.x += a.x + b.x; acc.y += a.y + b.y;
        acc.z += a.z + b.z; acc.w += a.w + b.w;
    }
    if (e < r1) {
        float4 a = ((const float4*)(X + (size_t)g_csr[e] * C_OUT))[lane];
        acc.x += a.x; acc.y += a.y; acc.z += a.z; acc.w += a.w;
    }
    ((float4*)(OUT + (size_t)node * C_OUT))[lane] = acc;
}

// ---------------------------------------------------------------------------
// Merged pre-conversion: weight transposes (coalesced via 64x64 smem tiles)
// + x split into A1[:, 256:512].
//   blocks [0,64):  Bt1 tiles (8n x 8k of 64)
//   blocks [64,96): Bt2 tiles (4n x 8k of 64)
//   blocks [96,..): x convert, 256 two-col units per block
// ---------------------------------------------------------------------------
__global__ void prep_inputs(const float* __restrict__ x,
                            const float* __restrict__ W1l, const float* __restrict__ W1r,
                            const float* __restrict__ W2l, const float* __restrict__ W2r,
                            int M) {
    const int b = blockIdx.x;
    const int tid = threadIdx.x;

    if (b >= 96) {
        int p = (b - 96) * 256 + tid;
        if (p < M * 128) {
            int m = p >> 7;
            int c2 = (p & 127) * 2;
            float a  = x[m * 256 + c2];
            float bb = x[m * 256 + c2 + 1];
            uint32_t h2, l2;
            split2(a, bb, h2, l2);
            *(uint32_t*)(g_A1h + (size_t)m * KCAT + 256 + c2) = h2;
            *(uint32_t*)(g_A1l + (size_t)m * KCAT + 256 + c2) = l2;
        }
        return;
    }

    __shared__ float tile[64][65];    // [n_local][k_local]
    const float* W;
    __nv_bfloat16 *Dh, *Dl;
    int ldw, roff, coff, nt, kt;
    if (b < 64) {                     // layer-1 weights -> g_B1 [512][512]
        nt = (b & 7) * 64; kt = (b >> 3) * 64;
        if (kt < 256) { W = W1l; roff = kt; } else { W = W1r; roff = kt - 256; }
        ldw = 512; coff = nt;
        Dh = g_B1h; Dl = g_B1l;
    } else {                          // layer-2 weights -> g_B2 [256][512]
        int t = b - 64;
        nt = (t & 3) * 64; kt = (t >> 2) * 64;
        if (nt < 128) { W = W2l; coff = nt; } else { W = W2r; coff = nt - 128; }
        ldw = 128; roff = kt;
        Dh = g_B2h; Dl = g_B2l;
    }
    // Coalesced read: 4 k-rows x 64 n per pass.
#pragma unroll
    for (int pass = 0; pass < 16; ++pass) {
        int r = pass * 4 + (tid >> 6);
        int c = tid & 63;
        tile[c][r] = W[(size_t)(roff + r) * ldw + coff + c];
    }
    __syncthreads();
    // Coalesced write: 8 n-rows per pass, 32 lanes x 2 bf16 = 128B contiguous.
#pragma unroll
    for (int pass = 0; pass < 8; ++pass) {
        int n0 = pass * 8 + (tid >> 5);
        int k0 = (tid & 31) * 2;
        uint32_t h2, l2;
        split2(tile[n0][k0], tile[n0][k0 + 1], h2, l2);
        size_t off = (size_t)(nt + n0) * KCAT + kt + k0;
        *(uint32_t*)(Dh + off) = h2;
        *(uint32_t*)(Dl + off) = l2;
    }
}

// ---------------------------------------------------------------------------
// HMMA bf16-split GEMM.  Tile 128x64, BK=64, 8 warps (4m x 2n), warp 32x32.
// 96KB smem double buffer -> 2 CTAs/SM.
// MODE 0 (layer1): C = relu(A@B + bias); write split bf16 to Hh/Hl [M][512]
// MODE 1 (layer2): cols <128 -> P (no bias); cols >=128 -> OUT (+b2).
// ---------------------------------------------------------------------------
#define STAGE_BYTES 49152
#define GSMEM (2 * STAGE_BYTES)   // Ah16K, Al16K, Bh8K, Bl8K per stage

template <int MODE>
__global__ void __launch_bounds__(256, 2)
gemm_mma(const __nv_bfloat16* __restrict__ Ah, const __nv_bfloat16* __restrict__ Al,
         const __nv_bfloat16* __restrict__ Bh, const __nv_bfloat16* __restrict__ Bl,
         const float* __restrict__ bias,       // MODE0: b1
         __nv_bfloat16* __restrict__ Hh, __nv_bfloat16* __restrict__ Hl,
         float* __restrict__ P, float* __restrict__ OUT,
         const float* __restrict__ b2, int M) {
    extern __shared__ char smem_raw[];
    const uint32_t sb = smem_u32(smem_raw);
    const int tid  = threadIdx.x;
    const int lane = tid & 31;
    const int w    = tid >> 5;
    const int wm   = w & 3;          // 4 m-blocks of 32
    const int wn   = w >> 2;         // 2 n-blocks of 32
    const int bm   = blockIdx.y * 128;
    const int bn   = blockIdx.x * 64;
    constexpr int T = KCAT / 64;     // 8

    float acc[2][4][4];
#pragma unroll
    for (int i = 0; i < 2; ++i)
#pragma unroll
        for (int j = 0; j < 4; ++j)
#pragma unroll
            for (int c = 0; c < 4; ++c) acc[i][j][c] = 0.f;

    auto load_tile = [&](int t, int s) {
        const int kk = t * 64;
        const uint32_t b0 = sb + s * STAGE_BYTES;
        const uint32_t dAh = b0, dAl = b0 + 16384, dBh = b0 + 32768, dBl = b0 + 40960;
#pragma unroll
        for (int i = 0; i < 4; ++i) {                 // A: 1024 chunks (128 rows x 8)
            int idx = tid + i * 256;
            int row = idx >> 3, c = idx & 7;
            int gm = bm + row;
            uint32_t off = swz(row * 128 + c * 16);
            int sz = (gm < M) ? 16 : 0;
            const char* pa = (const char*)(Ah + (size_t)gm * KCAT + kk + c * 8);
            const char* pl = (const char*)(Al + (size_t)gm * KCAT + kk + c * 8);
            CP_ASYNC16(dAh + off, pa, sz);
            CP_ASYNC16(dAl + off, pl, sz);
        }
#pragma unroll
        for (int i = 0; i < 2; ++i) {                 // B: 512 chunks (64 n-rows x 8)
            int idx = tid + i * 256;
            int row = idx >> 3, c = idx & 7;
            int gn = bn + row;
            uint32_t off = swz(row * 128 + c * 16);
            const char* pb = (const char*)(Bh + (size_t)gn * KCAT + kk + c * 8);
            const char* pl = (const char*)(Bl + (size_t)gn * KCAT + kk + c * 8);
            CP_ASYNC16(dBh + off, pb, 16);
            CP_ASYNC16(dBl + off, pl, 16);
        }
    };

    const int lr16 = lane & 15;
    const int lc8  = (lane >> 4) * 8;

    auto compute = [&](int s) {
        const uint32_t b0 = sb + s * STAGE_BYTES;
        const uint32_t aH = b0, aL = b0 + 16384, bH = b0 + 32768, bL = b0 + 40960;
#pragma unroll
        for (int ks = 0; ks < 4; ++ks) {
            const int k0 = ks * 16;
            uint32_t ah[2][4], al[2][4];
#pragma unroll
            for (int i = 0; i < 2; ++i) {
                uint32_t off = swz((uint32_t)((wm * 32 + i * 16 + lr16) * 128 + (k0 + lc8) * 2));
                LDSM_X4(ah[i][0], ah[i][1], ah[i][2], ah[i][3], aH + off);
                LDSM_X4(al[i][0], al[i][1], al[i][2], al[i][3], aL + off);
            }
            uint32_t bh[4][2], bl[4][2];
#pragma unroll
            for (int jp = 0; jp < 2; ++jp) {
                uint32_t off = swz((uint32_t)((wn * 32 + jp * 16 + lr16) * 128 + (k0 + lc8) * 2));
                uint32_t q0, q1, q2, q3;
                LDSM_X4(q0, q1, q2, q3, bH + off);
                bh[2 * jp][0] = q0; bh[2 * jp][1] = q2;
                bh[2 * jp + 1][0] = q1; bh[2 * jp + 1][1] = q3;
                LDSM_X4(q0, q1, q2, q3, bL + off);
                bl[2 * jp][0] = q0; bl[2 * jp][1] = q2;
                bl[2 * jp + 1][0] = q1; bl[2 * jp + 1][1] = q3;
            }
#pragma unroll
            for (int i = 0; i < 2; ++i)
#pragma unroll
                for (int j = 0; j < 4; ++j) {
                    mma16816(acc[i][j], ah[i][0], ah[i][1], ah[i][2], ah[i][3],
                             bh[j][0], bh[j][1]);
                    mma16816(acc[i][j], ah[i][0], ah[i][1], ah[i][2], ah[i][3],
                             bl[j][0], bl[j][1]);
                    mma16816(acc[i][j], al[i][0], al[i][1], al[i][2], al[i][3],
                             bh[j][0], bh[j][1]);
                }
        }
    };

    load_tile(0, 0);
    CP_COMMIT();
    for (int t = 0; t < T; ++t) {
        const int s = t & 1;
        CP_WAIT0();
        __syncthreads();
        if (t + 1 < T) { load_tile(t + 1, s ^ 1); CP_COMMIT(); }
        compute(s);
        __syncthreads();
    }

    // ---- epilogue ----
#pragma unroll
    for (int i = 0; i < 2; ++i) {
        const int m0 = bm + wm * 32 + i * 16 + (lane >> 2);
#pragma unroll
        for (int j = 0; j < 4; ++j) {
            const int n = bn + wn * 32 + j * 8 + (lane & 3) * 2;
            if (MODE == 0) {
                float2 bb = *(const float2*)(bias + n);
                float v0 = fmaxf(acc[i][j][0] + bb.x, 0.f);
                float v1 = fmaxf(acc[i][j][1] + bb.y, 0.f);
                float v2 = fmaxf(acc[i][j][2] + bb.x, 0.f);
                float v3 = fmaxf(acc[i][j][3] + bb.y, 0.f);
                uint32_t h2, l2;
                if (m0 < M) {
                    split2(v0, v1, h2, l2);
                    *(uint32_t*)(Hh + (size_t)m0 * KCAT + n) = h2;
                    *(uint32_t*)(Hl + (size_t)m0 * KCAT + n) = l2;
                }
                if (m0 + 8 < M) {
                    split2(v2, v3, h2, l2);
                    *(uint32_t*)(Hh + (size_t)(m0 + 8) * KCAT + n) = h2;
                    *(uint32_t*)(Hl + (size_t)(m0 + 8) * KCAT + n) = l2;
                }
            } else {
                float* Csel = (n < 128) ? P : OUT;
                const int cn = (n < 128) ? n : (n - 128);
                float bx = 0.f, by = 0.f;
                if (n >= 128) { float2 bb = *(const float2*)(b2 + cn); bx = bb.x; by = bb.y; }
                if (m0 < M)
                    *(float2*)(Csel + (size_t)m0 * C_OUT + cn) =
                        make_float2(acc[i][j][0] + bx, acc[i][j][1] + by);
                if (m0 + 8 < M)
                    *(float2*)(Csel + (size_t)(m0 + 8) * C_OUT + cn) =
                        make_float2(acc[i][j][2] + bx, acc[i][j][3] + by);
            }
        }
    }
}

// ---------------------------------------------------------------------------
extern "C" void kernel_launch(void* const* d_in, const int* in_sizes, int n_in,
                              void* d_out, int out_size) {
    const float* x   = (const float*)d_in[0];
    const void*  ei  = d_in[1];
    const float* W1l = (const float*)d_in[2];
    const float* b1  = (const float*)d_in[3];
    const float* W1r = (const float*)d_in[4];
    const float* W2l = (const float*)d_in[5];
    const float* b2  = (const float*)d_in[6];
    const float* W2r = (const float*)d_in[7];
    float*       out = (float*)d_out;

    const int M = in_sizes[0] / F_IN;    // 10000
    const int E = in_sizes[1] / 2;       // 320000

    float* P;
    __nv_bfloat16 *A1h, *A1l, *Hh, *Hl, *B1h, *B1l, *B2h, *B2l;
    cudaGetSymbolAddress((void**)&P,   g_P);
    cudaGetSymbolAddress((void**)&A1h, g_A1h);
    cudaGetSymbolAddress((void**)&A1l, g_A1l);
    cudaGetSymbolAddress((void**)&Hh,  g_Hh);
    cudaGetSymbolAddress((void**)&Hl,  g_Hl);
    cudaGetSymbolAddress((void**)&B1h, g_B1h);
    cudaGetSymbolAddress((void**)&B1l, g_B1l);
    cudaGetSymbolAddress((void**)&B2h, g_B2h);
    cudaGetSymbolAddress((void**)&B2l, g_B2l);

    static int smem_set = 0;
    if (!smem_set) {
        cudaFuncSetAttribute(gemm_mma<0>, cudaFuncAttributeMaxDynamicSharedMemorySize, GSMEM);
        cudaFuncSetAttribute(gemm_mma<1>, cudaFuncAttributeMaxDynamicSharedMemorySize, GSMEM);
        smem_set = 1;
    }

    // ---- CSR build ----
    detect_and_zero<<<1, 256>>>((const int*)ei, (2 * E < 2048) ? 2 * E : 2048);
    convert_edges_hist<<<(E + 255) / 256, 256>>>(ei, E);
    build_rowptr<<<1, 1024>>>();
    fill_csr<<<(E + 255) / 256, 256>>>(E);

    // ---- merged pre-conversion (weights transposed + x split) ----
    prep_inputs<<<96 + (M * 128 + 255) / 256, 256>>>(x, W1l, W1r, W2l, W2r, M);

    // ---- Layer 1: A1[:,0:256] = split(segsum(x)) (fused);
    //      h(split) = relu(A1 @ [W1l;W1r] + b1) ----
    gather_splitA<<<(M * 32 + 255) / 256, 256>>>(x, M);
    {
        dim3 grid(HID / 64, (M + 127) / 128);   // (8, 79)
        gemm_mma<0><<<grid, 256, GSMEM>>>(A1h, A1l, B1h, B1l, b1,
                                          Hh, Hl, nullptr, nullptr, nullptr, M);
    }

    // ---- Layer 2 (linearity reorder): [P|out] = h @ [W2l|W2r] (+b2 on out);
    //      out += segsum(P) ----
    {
        dim3 grid(2 * C_OUT / 64, (M + 127) / 128);  // (4, 79)
        gemm_mma<1><<<grid, 256, GSMEM>>>(Hh, Hl, B2h, B2l, nullptr,
                                          nullptr, nullptr, P, out, b2, M);
    }
    gather_P<<<(M * 32 + 255) / 256, 256>>>(P, out, M);
}

// round 12
// speedup vs baseline: 3.0856x; 1.0512x over previous
#include <cuda_runtime.h>
#include <cuda_bf16.h>
#include <cstdint>

#define NNODES 10000
#define F_IN   256
#define HID    512
#define C_OUT  128
#define NEDGES 320000
#define KCAT   512            // K for both fused GEMMs

// ---------------------------------------------------------------------------
// Scratch (allocation-free rule: __device__ globals)
// g_deg relies on: zero-initialized at load; re-zeroed by build_rowptr after
// each consume -> every invocation (incl. graph replays) sees zeros.
// ---------------------------------------------------------------------------
__device__ __align__(1024) float g_P   [NNODES * C_OUT];         // h @ W2l fp32
__device__ __align__(1024) __nv_bfloat16 g_A1h[NNODES * KCAT];   // [agg1|x] hi
__device__ __align__(1024) __nv_bfloat16 g_A1l[NNODES * KCAT];   // [agg1|x] lo
__device__ __align__(1024) __nv_bfloat16 g_Hh [NNODES * KCAT];   // h hi
__device__ __align__(1024) __nv_bfloat16 g_Hl [NNODES * KCAT];   // h lo
__device__ __align__(1024) __nv_bfloat16 g_B1h[HID * KCAT];      // [W1l;W1r]^T hi [512][512]
__device__ __align__(1024) __nv_bfloat16 g_B1l[HID * KCAT];
__device__ __align__(1024) __nv_bfloat16 g_B2h[(2 * C_OUT) * KCAT]; // [W2l|W2r]^T hi [256][512]
__device__ __align__(1024) __nv_bfloat16 g_B2l[(2 * C_OUT) * KCAT];
__device__ int g_src[NEDGES];
__device__ int g_dst[NEDGES];
__device__ int g_seq[NEDGES];       // per-dest sequence number (from hist atomic)
__device__ int g_deg[NNODES];
__device__ int g_rowptr[NNODES + 1];
__device__ int g_csr[NEDGES];

// ---------------------------------------------------------------------------
// PTX helpers (plain sm_80+ PTX; NO sm_103a-only features — harness targets sm_103)
// ---------------------------------------------------------------------------
__device__ __forceinline__ uint32_t smem_u32(const void* p) {
    uint32_t a;
    asm("{ .reg .u64 t; cvta.to.shared.u64 t, %1; cvt.u32.u64 %0, t; }"
        : "=r"(a) : "l"(p));
    return a;
}
#define CP_ASYNC16(dst, src, sz) \
    asm volatile("cp.async.cg.shared.global [%0], [%1], 16, %2;" \
                 :: "r"(dst), "l"(src), "r"(sz) : "memory")
#define CP_COMMIT() asm volatile("cp.async.commit_group;" ::: "memory")
#define CP_WAIT0()  asm volatile("cp.async.wait_group 0;" ::: "memory")
#define LDSM_X4(r0, r1, r2, r3, addr) \
    asm volatile("ldmatrix.sync.aligned.m8n8.x4.shared.b16 {%0,%1,%2,%3}, [%4];" \
                 : "=r"(r0), "=r"(r1), "=r"(r2), "=r"(r3) : "r"(addr))

__device__ __forceinline__ void mma16816(float c[4],
                                         uint32_t a0, uint32_t a1, uint32_t a2, uint32_t a3,
                                         uint32_t b0, uint32_t b1) {
    asm volatile(
        "mma.sync.aligned.m16n8k16.row.col.f32.bf16.bf16.f32 "
        "{%0,%1,%2,%3}, {%4,%5,%6,%7}, {%8,%9}, {%0,%1,%2,%3};"
        : "+f"(c[0]), "+f"(c[1]), "+f"(c[2]), "+f"(c[3])
        : "r"(a0), "r"(a1), "r"(a2), "r"(a3), "r"(b0), "r"(b1));
}

__device__ __forceinline__ uint32_t swz(uint32_t off) {   // SW128-style XOR
    return off ^ ((off >> 3) & 0x70);
}

__device__ __forceinline__ void split2(float a, float b, uint32_t& h2o, uint32_t& l2o) {
    __nv_bfloat162 hv, lv;
    hv.x = __float2bfloat16(a);
    hv.y = __float2bfloat16(b);
    lv.x = __float2bfloat16(a - __bfloat162float(hv.x));
    lv.y = __float2bfloat16(b - __bfloat162float(hv.y));
    h2o = *reinterpret_cast<uint32_t*>(&hv);
    l2o = *reinterpret_cast<uint32_t*>(&lv);
}

__device__ __forceinline__ int clampi(long long v, int hi) {
    int r = (int)v;
    if (v < 0) r = 0;
    if (v >= hi) r = hi - 1;
    return r;
}

// ---------------------------------------------------------------------------
// Front kernel: grid-partitioned independent work running concurrently.
//   blocks [0, eb):            edge decode (2 edges/thread) + degree hist + seq
//   blocks [eb, eb+96):        weight transpose + bf16 split (64x64 smem tiles)
//   blocks [eb+96, ...):       x split into A1[:, 256:512]
// Edge blocks self-detect the dtype (first 2048 int32 words: int64-LE < 2^31
// has all odd words zero; int32 random indices do not).
// ---------------------------------------------------------------------------
__global__ void convert_and_prep(const void* __restrict__ ei,
                                 const float* __restrict__ x,
                                 const float* __restrict__ W1l, const float* __restrict__ W1r,
                                 const float* __restrict__ W2l, const float* __restrict__ W2r,
                                 int eb, int E, int M) {
    const int b = blockIdx.x;
    const int tid = threadIdx.x;

    if (b < eb) {
        // ---- per-block dtype detection ----
        __shared__ int s_any;
        if (tid == 0) s_any = 0;
        __syncthreads();
        const int* p32 = (const int*)ei;
        int n_check = (2 * E < 2048) ? 2 * E : 2048;
        int any = 0;
        for (int i = 2 * tid + 1; i < n_check; i += 512) any |= p32[i];
        if (any) atomicOr(&s_any, 1);
        __syncthreads();
        const int is32 = s_any;

        // ---- decode 2 edges/thread, vectorized ----
        int e0 = (b * 256 + tid) * 2;
        if (e0 + 1 < E) {
            long long s0, s1, d0, d1;
            if (is32) {
                int2 sp = *(const int2*)(p32 + e0);
                int2 dp = *(const int2*)(p32 + E + e0);
                s0 = sp.x; s1 = sp.y; d0 = dp.x; d1 = dp.y;
            } else {
                const long long* p64 = (const long long*)ei;
                longlong2 sp = *(const longlong2*)(p64 + e0);
                longlong2 dp = *(const longlong2*)(p64 + E + e0);
                s0 = sp.x; s1 = sp.y; d0 = dp.x; d1 = dp.y;
            }
            int si0 = clampi(s0, NNODES), si1 = clampi(s1, NNODES);
            int di0 = clampi(d0, NNODES), di1 = clampi(d1, NNODES);
            *(int2*)(g_src + e0) = make_int2(si0, si1);
            *(int2*)(g_dst + e0) = make_int2(di0, di1);
            int q0 = atomicAdd(&g_deg[di0], 1);
            int q1 = atomicAdd(&g_deg[di1], 1);
            *(int2*)(g_seq + e0) = make_int2(q0, q1);
        }
        return;
    }

    if (b < eb + 96) {
        // ---- weight transpose + split via smem tile (both directions coalesced) ----
        const int wb = b - eb;
        __shared__ float tile[64][65];
        const float* W;
        __nv_bfloat16 *Dh, *Dl;
        int ldw, roff, coff, nt, kt;
        if (wb < 64) {                 // layer-1 weights -> g_B1 [512][512]
            nt = (wb & 7) * 64; kt = (wb >> 3) * 64;
            if (kt < 256) { W = W1l; roff = kt; } else { W = W1r; roff = kt - 256; }
            ldw = 512; coff = nt;
            Dh = g_B1h; Dl = g_B1l;
        } else {                       // layer-2 weights -> g_B2 [256][512]
            int t = wb - 64;
            nt = (t & 3) * 64; kt = (t >> 2) * 64;
            if (nt < 128) { W = W2l; coff = nt; } else { W = W2r; coff = nt - 128; }
            ldw = 128; roff = kt;
            Dh = g_B2h; Dl = g_B2l;
        }
#pragma unroll
        for (int pass = 0; pass < 16; ++pass) {
            int r = pass * 4 + (tid >> 6);
            int c = tid & 63;
            tile[c][r] = W[(size_t)(roff + r) * ldw + coff + c];
        }
        __syncthreads();
#pragma unroll
        for (int pass = 0; pass < 8; ++pass) {
            int n0 = pass * 8 + (tid >> 5);
            int k0 = (tid & 31) * 2;
            uint32_t h2, l2;
            split2(tile[n0][k0], tile[n0][k0 + 1], h2, l2);
            size_t off = (size_t)(nt + n0) * KCAT + kt + k0;
            *(uint32_t*)(Dh + off) = h2;
            *(uint32_t*)(Dl + off) = l2;
        }
        return;
    }

    // ---- x split into A1[:, 256:512] ----
    int p = (b - eb - 96) * 256 + tid;
    if (p < M * 128) {
        int m = p >> 7;
        int c2 = (p & 127) * 2;
        float a  = x[m * 256 + c2];
        float bb = x[m * 256 + c2 + 1];
        uint32_t h2, l2;
        split2(a, bb, h2, l2);
        *(uint32_t*)(g_A1h + (size_t)m * KCAT + 256 + c2) = h2;
        *(uint32_t*)(g_A1l + (size_t)m * KCAT + 256 + c2) = l2;
    }
}

// ---------------------------------------------------------------------------
// Exclusive scan of g_deg -> g_rowptr (coalesced via smem staging).
// Also RE-ZEROES g_deg for the next invocation (each thread rewrites exactly
// the indices it loaded -> no cross-thread hazard).
// ---------------------------------------------------------------------------
__global__ void build_rowptr() {
    __shared__ int sdeg[NNODES];      // 40 KB
    __shared__ int wsum[32];
    const int t = threadIdx.x;
    const int lane = t & 31, w = t >> 5;

    for (int i = t; i < NNODES; i += 1024) {
        sdeg[i] = g_deg[i];
        g_deg[i] = 0;                 // reset for next graph replay
    }
    __syncthreads();

    const int base = t * 16;
    int local[16];
    int s = 0;
#pragma unroll
    for (int i = 0; i < 16; ++i) {
        int idx = base + i;
        int v = (idx < NNODES) ? sdeg[idx] : 0;
        local[i] = s; s += v;
    }
    int inc = s;
#pragma unroll
    for (int o = 1; o < 32; o <<= 1) {
        int v = __shfl_up_sync(0xffffffffu, inc, o);
        if (lane >= o) inc += v;
    }
    if (lane == 31) wsum[w] = inc;
    __syncthreads();
    if (w == 0) {
        int v2 = wsum[lane];
#pragma unroll
        for (int o = 1; o < 32; o <<= 1) {
            int u = __shfl_up_sync(0xffffffffu, v2, o);
            if (lane >= o) v2 += u;
        }
        wsum[lane] = v2;
    }
    __syncthreads();
    int excl = inc - s + (w ? wsum[w - 1] : 0);
#pragma unroll
    for (int i = 0; i < 16; ++i) {
        int idx = base + i;
        if (idx < NNODES) sdeg[idx] = excl + local[i];
    }
    __syncthreads();
    for (int i = t; i < NNODES; i += 1024) g_rowptr[i] = sdeg[i];
    if (t == 1023) g_rowptr[NNODES] = wsum[31];
}

// Atomic-free CSR fill, 4 edges/thread (MLP=4 to hide rowptr/store latency).
__global__ void fill_csr(int E) {
    int e0 = (blockIdx.x * blockDim.x + threadIdx.x) * 4;
    if (e0 + 3 < E) {
        int4 d = *(const int4*)(g_dst + e0);
        int4 q = *(const int4*)(g_seq + e0);
        int4 s = *(const int4*)(g_src + e0);
        int r0 = g_rowptr[d.x];
        int r1 = g_rowptr[d.y];
        int r2 = g_rowptr[d.z];
        int r3 = g_rowptr[d.w];
        g_csr[r0 + q.x] = s.x;
        g_csr[r1 + q.y] = s.y;
        g_csr[r2 + q.z] = s.z;
        g_csr[r3 + q.w] = s.w;
    } else {
        for (int e = e0; e < E; ++e)
            g_csr[g_rowptr[g_dst[e]] + g_seq[e]] = g_src[e];
    }
}

// ---------------------------------------------------------------------------
// Layer-1 gather fused with bf16 split: A1[:, 0:256] = split(segsum(x)).
// ---------------------------------------------------------------------------
__global__ void gather_splitA(const float* __restrict__ X, int Nn) {
    int node = (blockIdx.x * blockDim.x + threadIdx.x) >> 5;
    if (node >= Nn) return;
    int lane = threadIdx.x & 31;
    int r0 = g_rowptr[node];
    int r1 = g_rowptr[node + 1];

    float4 acc[2];
    acc[0] = make_float4(0.f, 0.f, 0.f, 0.f);
    acc[1] = make_float4(0.f, 0.f, 0.f, 0.f);

    int e = r0;
    for (; e + 1 < r1; e += 2) {
        const float4* p0 = (const float4*)(X + (size_t)g_csr[e] * F_IN);
        const float4* p1 = (const float4*)(X + (size_t)g_csr[e + 1] * F_IN);
#pragma unroll
        for (int j = 0; j < 2; ++j) {
            float4 a = p0[lane + 32 * j];
            float4 b = p1[lane + 32 * j];
            acc[j].x += a.x + b.x;
            acc[j].y += a.y + b.y;
            acc[j].z += a.z + b.z;
            acc[j].w += a.w + b.w;
        }
    }
    if (e < r1) {
        const float4* p0 = (const float4*)(X + (size_t)g_csr[e] * F_IN);
#pragma unroll
        for (int j = 0; j < 2; ++j) {
            float4 a = p0[lane + 32 * j];
            acc[j].x += a.x; acc[j].y += a.y;
            acc[j].z += a.z; acc[j].w += a.w;
        }
    }

#pragma unroll
    for (int j = 0; j < 2; ++j) {
        int col = (lane + 32 * j) * 4;
        uint32_t h0, l0, h1, l1;
        split2(acc[j].x, acc[j].y, h0, l0);
        split2(acc[j].z, acc[j].w, h1, l1);
        *(uint2*)(g_A1h + (size_t)node * KCAT + col) = make_uint2(h0, h1);
        *(uint2*)(g_A1l + (size_t)node * KCAT + col) = make_uint2(l0, l1);
    }
}

// P-gather: out[node] += segsum(P), F=128, fp32.
__global__ void gather_P(const float* __restrict__ X, float* __restrict__ OUT, int Nn) {
    int node = (blockIdx.x * blockDim.x + threadIdx.x) >> 5;
    if (node >= Nn) return;
    int lane = threadIdx.x & 31;
    int r0 = g_rowptr[node];
    int r1 = g_rowptr[node + 1];

    float4 acc = ((const float4*)(OUT + (size_t)node * C_OUT))[lane];
    int e = r0;
    for (; e + 1 < r1; e += 2) {
        float4 a = ((const float4*)(X + (size_t)g_csr[e] * C_OUT))[lane];
        float4 b = ((const float4*)(X + (size_t)g_csr[e + 1] * C_OUT))[lane];
        acc.x += a.x + b.x; acc.y += a.y + b.y;
        acc.z += a.z + b.z; acc.w += a.w + b.w;
    }
    if (e < r1) {
        float4 a = ((const float4*)(X + (size_t)g_csr[e] * C_OUT))[lane];
        acc.x += a.x; acc.y += a.y; acc.z += a.z; acc.w += a.w;
    }
    ((float4*)(OUT + (size_t)node * C_OUT))[lane] = acc;
}

// ---------------------------------------------------------------------------
// HMMA bf16-split GEMM.  Tile 128x64, BK=64, 8 warps (4m x 2n), warp 32x32.
// 96KB smem double buffer -> 2 CTAs/SM.
// MODE 0 (layer1): C = relu(A@B + bias); write split bf16 to Hh/Hl [M][512]
// MODE 1 (layer2): cols <128 -> P (no bias); cols >=128 -> OUT (+b2).
// ---------------------------------------------------------------------------
#define STAGE_BYTES 49152
#define GSMEM (2 * STAGE_BYTES)   // Ah16K, Al16K, Bh8K, Bl8K per stage

template <int MODE>
__global__ void __launch_bounds__(256, 2)
gemm_mma(const __nv_bfloat16* __restrict__ Ah, const __nv_bfloat16* __restrict__ Al,
         const __nv_bfloat16* __restrict__ Bh, const __nv_bfloat16* __restrict__ Bl,
         const float* __restrict__ bias,       // MODE0: b1
         __nv_bfloat16* __restrict__ Hh, __nv_bfloat16* __restrict__ Hl,
         float* __restrict__ P, float* __restrict__ OUT,
         const float* __restrict__ b2, int M) {
    extern __shared__ char smem_raw[];
    const uint32_t sb = smem_u32(smem_raw);
    const int tid  = threadIdx.x;
    const int lane = tid & 31;
    const int w    = tid >> 5;
    const int wm   = w & 3;          // 4 m-blocks of 32
    const int wn   = w >> 2;         // 2 n-blocks of 32
    const int bm   = blockIdx.y * 128;
    const int bn   = blockIdx.x * 64;
    constexpr int T = KCAT / 64;     // 8

    float acc[2][4][4];
#pragma unroll
    for (int i = 0; i < 2; ++i)
#pragma unroll
        for (int j = 0; j < 4; ++j)
#pragma unroll
            for (int c = 0; c < 4; ++c) acc[i][j][c] = 0.f;

    auto load_tile = [&](int t, int s) {
        const int kk = t * 64;
        const uint32_t b0 = sb + s * STAGE_BYTES;
        const uint32_t dAh = b0, dAl = b0 + 16384, dBh = b0 + 32768, dBl = b0 + 40960;
#pragma unroll
        for (int i = 0; i < 4; ++i) {                 // A: 1024 chunks (128 rows x 8)
            int idx = tid + i * 256;
            int row = idx >> 3, c = idx & 7;
            int gm = bm + row;
            uint32_t off = swz(row * 128 + c * 16);
            int sz = (gm < M) ? 16 : 0;
            const char* pa = (const char*)(Ah + (size_t)gm * KCAT + kk + c * 8);
            const char* pl = (const char*)(Al + (size_t)gm * KCAT + kk + c * 8);
            CP_ASYNC16(dAh + off, pa, sz);
            CP_ASYNC16(dAl + off, pl, sz);
        }
#pragma unroll
        for (int i = 0; i < 2; ++i) {                 // B: 512 chunks (64 n-rows x 8)
            int idx = tid + i * 256;
            int row = idx >> 3, c = idx & 7;
            int gn = bn + row;
            uint32_t off = swz(row * 128 + c * 16);
            const char* pb = (const char*)(Bh + (size_t)gn * KCAT + kk + c * 8);
            const char* pl = (const char*)(Bl + (size_t)gn * KCAT + kk + c * 8);
            CP_ASYNC16(dBh + off, pb, 16);
            CP_ASYNC16(dBl + off, pl, 16);
        }
    };

    const int lr16 = lane & 15;
    const int lc8  = (lane >> 4) * 8;

    auto compute = [&](int s) {
        const uint32_t b0 = sb + s * STAGE_BYTES;
        const uint32_t aH = b0, aL = b0 + 16384, bH = b0 + 32768, bL = b0 + 40960;
#pragma unroll
        for (int ks = 0; ks < 4; ++ks) {
            const int k0 = ks * 16;
            uint32_t ah[2][4], al[2][4];
#pragma unroll
            for (int i = 0; i < 2; ++i) {
                uint32_t off = swz((uint32_t)((wm * 32 + i * 16 + lr16) * 128 + (k0 + lc8) * 2));
                LDSM_X4(ah[i][0], ah[i][1], ah[i][2], ah[i][3], aH + off);
                LDSM_X4(al[i][0], al[i][1], al[i][2], al[i][3], aL + off);
            }
            uint32_t bh[4][2], bl[4][2];
#pragma unroll
            for (int jp = 0; jp < 2; ++jp) {
                uint32_t off = swz((uint32_t)((wn * 32 + jp * 16 + lr16) * 128 + (k0 + lc8) * 2));
                uint32_t q0, q1, q2, q3;
                LDSM_X4(q0, q1, q2, q3, bH + off);
                bh[2 * jp][0] = q0; bh[2 * jp][1] = q2;
                bh[2 * jp + 1][0] = q1; bh[2 * jp + 1][1] = q3;
                LDSM_X4(q0, q1, q2, q3, bL + off);
                bl[2 * jp][0] = q0; bl[2 * jp][1] = q2;
                bl[2 * jp + 1][0] = q1; bl[2 * jp + 1][1] = q3;
            }
#pragma unroll
            for (int i = 0; i < 2; ++i)
#pragma unroll
                for (int j = 0; j < 4; ++j) {
                    mma16816(acc[i][j], ah[i][0], ah[i][1], ah[i][2], ah[i][3],
                             bh[j][0], bh[j][1]);
                    mma16816(acc[i][j], ah[i][0], ah[i][1], ah[i][2], ah[i][3],
                             bl[j][0], bl[j][1]);
                    mma16816(acc[i][j], al[i][0], al[i][1], al[i][2], al[i][3],
                             bh[j][0], bh[j][1]);
                }
        }
    };

    load_tile(0, 0);
    CP_COMMIT();
    for (int t = 0; t < T; ++t) {
        const int s = t & 1;
        CP_WAIT0();
        __syncthreads();
        if (t + 1 < T) { load_tile(t + 1, s ^ 1); CP_COMMIT(); }
        compute(s);
        __syncthreads();
    }

    // ---- epilogue ----
#pragma unroll
    for (int i = 0; i < 2; ++i) {
        const int m0 = bm + wm * 32 + i * 16 + (lane >> 2);
#pragma unroll
        for (int j = 0; j < 4; ++j) {
            const int n = bn + wn * 32 + j * 8 + (lane & 3) * 2;
            if (MODE == 0) {
                float2 bb = *(const float2*)(bias + n);
                float v0 = fmaxf(acc[i][j][0] + bb.x, 0.f);
                float v1 = fmaxf(acc[i][j][1] + bb.y, 0.f);
                float v2 = fmaxf(acc[i][j][2] + bb.x, 0.f);
                float v3 = fmaxf(acc[i][j][3] + bb.y, 0.f);
                uint32_t h2, l2;
                if (m0 < M) {
                    split2(v0, v1, h2, l2);
                    *(uint32_t*)(Hh + (size_t)m0 * KCAT + n) = h2;
                    *(uint32_t*)(Hl + (size_t)m0 * KCAT + n) = l2;
                }
                if (m0 + 8 < M) {
                    split2(v2, v3, h2, l2);
                    *(uint32_t*)(Hh + (size_t)(m0 + 8) * KCAT + n) = h2;
                    *(uint32_t*)(Hl + (size_t)(m0 + 8) * KCAT + n) = l2;
                }
            } else {
                float* Csel = (n < 128) ? P : OUT;
                const int cn = (n < 128) ? n : (n - 128);
                float bx = 0.f, by = 0.f;
                if (n >= 128) { float2 bb = *(const float2*)(b2 + cn); bx = bb.x; by = bb.y; }
                if (m0 < M)
                    *(float2*)(Csel + (size_t)m0 * C_OUT + cn) =
                        make_float2(acc[i][j][0] + bx, acc[i][j][1] + by);
                if (m0 + 8 < M)
                    *(float2*)(Csel + (size_t)(m0 + 8) * C_OUT + cn) =
                        make_float2(acc[i][j][2] + bx, acc[i][j][3] + by);
            }
        }
    }
}

// ---------------------------------------------------------------------------
extern "C" void kernel_launch(void* const* d_in, const int* in_sizes, int n_in,
                              void* d_out, int out_size) {
    const float* x   = (const float*)d_in[0];
    const void*  ei  = d_in[1];
    const float* W1l = (const float*)d_in[2];
    const float* b1  = (const float*)d_in[3];
    const float* W1r = (const float*)d_in[4];
    const float* W2l = (const float*)d_in[5];
    const float* b2  = (const float*)d_in[6];
    const float* W2r = (const float*)d_in[7];
    float*       out = (float*)d_out;

    const int M = in_sizes[0] / F_IN;    // 10000
    const int E = in_sizes[1] / 2;       // 320000

    float* P;
    __nv_bfloat16 *A1h, *A1l, *Hh, *Hl, *B1h, *B1l, *B2h, *B2l;
    cudaGetSymbolAddress((void**)&P,   g_P);
    cudaGetSymbolAddress((void**)&A1h, g_A1h);
    cudaGetSymbolAddress((void**)&A1l, g_A1l);
    cudaGetSymbolAddress((void**)&Hh,  g_Hh);
    cudaGetSymbolAddress((void**)&Hl,  g_Hl);
    cudaGetSymbolAddress((void**)&B1h, g_B1h);
    cudaGetSymbolAddress((void**)&B1l, g_B1l);
    cudaGetSymbolAddress((void**)&B2h, g_B2h);
    cudaGetSymbolAddress((void**)&B2l, g_B2l);

    static int smem_set = 0;
    if (!smem_set) {
        cudaFuncSetAttribute(gemm_mma<0>, cudaFuncAttributeMaxDynamicSharedMemorySize, GSMEM);
        cudaFuncSetAttribute(gemm_mma<1>, cudaFuncAttributeMaxDynamicSharedMemorySize, GSMEM);
        smem_set = 1;
    }

    // ---- front kernel: edge decode + hist (blocks [0,eb)) running
    //      concurrently with all weight/x conversion blocks ----
    const int eb = (E + 511) / 512;
    const int xb = (M * 128 + 255) / 256;
    convert_and_prep<<<eb + 96 + xb, 256>>>(ei, x, W1l, W1r, W2l, W2r, eb, E, M);

    // ---- CSR: scan (+deg reset) then atomic-free fill ----
    build_rowptr<<<1, 1024>>>();
    fill_csr<<<(E / 4 + 255) / 256 + 1, 256>>>(E);

    // ---- Layer 1: A1[:,0:256] = split(segsum(x)) (fused);
    //      h(split) = relu(A1 @ [W1l;W1r] + b1) ----
    gather_splitA<<<(M * 32 + 255) / 256, 256>>>(x, M);
    {
        dim3 grid(HID / 64, (M + 127) / 128);   // (8, 79)
        gemm_mma<0><<<grid, 256, GSMEM>>>(A1h, A1l, B1h, B1l, b1,
                                          Hh, Hl, nullptr, nullptr, nullptr, M);
    }

    // ---- Layer 2 (linearity reorder): [P|out] = h @ [W2l|W2r] (+b2 on out);
    //      out += segsum(P) ----
    {
        dim3 grid(2 * C_OUT / 64, (M + 127) / 128);  // (4, 79)
        gemm_mma<1><<<grid, 256, GSMEM>>>(Hh, Hl, B2h, B2l, nullptr,
                                          nullptr, nullptr, P, out, b2, M);
    }
    gather_P<<<(M * 32 + 255) / 256, 256>>>(P, out, M);
}